// round 2
// baseline (speedup 1.0000x reference)
#include <cuda_runtime.h>
#include <cstdint>

// GIN: 5 layers, N=20000 nodes, E=320000 edges, HIDDEN=64, M=8.
// Strategy:
//  - Build CSR by dst once per launch (histogram + single-block scan + fill).
//  - Per layer: one fused kernel per 8 nodes (128 threads): CSR gather (applies
//    previous layer's BN affine on the fly), GEMM1+relu, GEMM2+relu, BN-stat
//    accumulation. GEMMs use packed fma.rn.f32x2 with pre-duplicated weights.
//  - BN folded to per-channel affine (scale, shift); finalize kernel per layer.
//  - Final: pool raw sums, apply affine, w_out, sigmoid.

#define N_NODES 20000
#define N_EDGES 320000
#define HID 64
#define MDIM 8
#define FEAT (HID*MDIM)   // 512 floats per node

typedef unsigned long long ull;

// ---------------- device scratch (no allocations allowed) ----------------
__device__ float g_bufA[N_NODES * FEAT];   // ~41 MB
__device__ float g_bufB[N_NODES * FEAT];   // ~41 MB
__device__ int   g_rowptr[N_NODES + 1];
__device__ int   g_count[N_NODES];
__device__ int   g_fill[N_NODES];
__device__ int   g_srce[N_EDGES];
__device__ float g_stats[5 * 128];         // per layer: sum[64], sumsq[64]
__device__ float g_affine[5 * 128];        // per layer: scale[64], shift[64]
__device__ ull   g_Wt1p[4 * 4096];         // W1 layers 1..4, [c][o], (w,w) pairs
__device__ ull   g_Wt2p[5 * 4096];         // W2 layers 0..4, [c][o], (w,w) pairs
__device__ float g_pool[FEAT];
__device__ int   g_is64;

// ---------------- f32x2 helpers ----------------
__device__ __forceinline__ ull pk2(float a, float b) {
    ull r; asm("mov.b64 %0, {%1, %2};" : "=l"(r) : "f"(a), "f"(b)); return r;
}
__device__ __forceinline__ float2 upk(ull v) {
    float2 r; asm("mov.b64 {%0, %1}, %2;" : "=f"(r.x), "=f"(r.y) : "l"(v)); return r;
}
__device__ __forceinline__ void fma2(ull& a, ull b, ull c) {
    asm("fma.rn.f32x2 %0, %1, %2, %0;" : "+l"(a) : "l"(b), "l"(c));
}

// ---------------- setup kernels ----------------
__global__ void k_init() {
    int i = blockIdx.x * blockDim.x + threadIdx.x;
    if (i < N_NODES) { g_count[i] = 0; g_fill[i] = 0; }
    if (i < 5 * 128) g_stats[i] = 0.f;
    if (i < FEAT)    g_pool[i] = 0.f;
}

// edge_index may be int64 (declared) or int32 (JAX x64-disabled). Detect.
__global__ void k_detect(const void* ei) {
    if (threadIdx.x == 0 && blockIdx.x == 0) {
        const ull* p = (const ull*)ei;
        int is64 = 1;
        for (int j = 0; j < 64; j++)
            if (p[j] >= (ull)N_NODES) is64 = 0;
        g_is64 = is64;
    }
}

__device__ __forceinline__ int edge_at(const void* ei, int idx) {
    return g_is64 ? (int)((const long long*)ei)[idx] : ((const int*)ei)[idx];
}

__global__ void k_hist(const void* ei) {
    int e = blockIdx.x * blockDim.x + threadIdx.x;
    if (e >= N_EDGES) return;
    atomicAdd(&g_count[edge_at(ei, N_EDGES + e)], 1);
}

__global__ void k_scan() {   // 1 block, 1024 threads, exclusive prefix over 20000
    __shared__ int s[1024];
    const int CH = 20;
    int t = threadIdx.x;
    int base = t * CH;
    int vals[CH];
    int local = 0;
#pragma unroll
    for (int j = 0; j < CH; j++) {
        int i = base + j;
        int v = (i < N_NODES) ? g_count[i] : 0;
        vals[j] = local; local += v;
    }
    s[t] = local;
    __syncthreads();
    for (int off = 1; off < 1024; off <<= 1) {
        int v = s[t];
        int add = (t >= off) ? s[t - off] : 0;
        __syncthreads();
        s[t] = v + add;
        __syncthreads();
    }
    int bb = (t == 0) ? 0 : s[t - 1];
#pragma unroll
    for (int j = 0; j < CH; j++) {
        int i = base + j;
        if (i < N_NODES) g_rowptr[i] = bb + vals[j];
    }
    if (t == 1023) g_rowptr[N_NODES] = s[1023];
}

__global__ void k_fill(const void* ei) {
    int e = blockIdx.x * blockDim.x + threadIdx.x;
    if (e >= N_EDGES) return;
    int srcv = edge_at(ei, e);
    int d    = edge_at(ei, N_EDGES + e);
    int pos  = g_rowptr[d] + atomicAdd(&g_fill[d], 1);
    g_srce[pos] = srcv;
}

// transpose + duplicate weights into (w,w) f32x2 pairs, layout [mat][c][o]
__global__ void k_prep(const float* __restrict__ w1, const float* __restrict__ w2) {
    int idx = blockIdx.x * blockDim.x + threadIdx.x;
    if (idx < 4 * 4096) {
        int mat = idx >> 12, r = idx & 4095, o = r >> 6, c = r & 63;
        float v = w1[idx];
        g_Wt1p[(mat << 12) + (c << 6) + o] = pk2(v, v);
    } else if (idx < 9 * 4096) {
        int j = idx - 4 * 4096;
        int mat = j >> 12, r = j & 4095, o = r >> 6, c = r & 63;
        float v = w2[j];
        g_Wt2p[(mat << 12) + (c << 6) + o] = pk2(v, v);
    }
}

// ---------------- GEMM core: out[o0..o0+3][m0..7] over K=64 ----------------
// sIn: shared, node-local [c][m] (512 floats). Wp: global pairs, pre-offset to o0.
__device__ __forceinline__ void gemm64(const float* sIn, const ull* __restrict__ Wp,
                                       ull acc[16]) {
#pragma unroll
    for (int i = 0; i < 16; i++) acc[i] = 0ULL;
#pragma unroll 8
    for (int c = 0; c < 64; c++) {
        ulonglong2 wa = *(const ulonglong2*)(Wp + (c << 6));
        ulonglong2 wb = *(const ulonglong2*)(Wp + (c << 6) + 2);
        ulonglong2 za = *(const ulonglong2*)(sIn + (c << 3));
        ulonglong2 zb = *(const ulonglong2*)(sIn + (c << 3) + 4);
        ull w0 = wa.x, w1 = wa.y, w2 = wb.x, w3 = wb.y;
        ull z0 = za.x, z1 = za.y, z2 = zb.x, z3 = zb.y;
        fma2(acc[0],  w0, z0); fma2(acc[1],  w0, z1); fma2(acc[2],  w0, z2); fma2(acc[3],  w0, z3);
        fma2(acc[4],  w1, z0); fma2(acc[5],  w1, z1); fma2(acc[6],  w1, z2); fma2(acc[7],  w1, z3);
        fma2(acc[8],  w2, z0); fma2(acc[9],  w2, z1); fma2(acc[10], w2, z2); fma2(acc[11], w2, z3);
        fma2(acc[12], w3, z0); fma2(acc[13], w3, z1); fma2(acc[14], w3, z2); fma2(acc[15], w3, z3);
    }
}

// relu(acc + b1) -> shared (y becomes next GEMM input)
__device__ __forceinline__ void epi1(const ull acc[16], const float* sB1,
                                     float* sZg, int o0) {
#pragma unroll
    for (int r = 0; r < 4; r++) {
        float b = sB1[o0 + r];
        float2 p0 = upk(acc[r * 4 + 0]), p1 = upk(acc[r * 4 + 1]);
        float2 p2 = upk(acc[r * 4 + 2]), p3 = upk(acc[r * 4 + 3]);
        float4 v0, v1;
        v0.x = fmaxf(p0.x + b, 0.f); v0.y = fmaxf(p0.y + b, 0.f);
        v0.z = fmaxf(p1.x + b, 0.f); v0.w = fmaxf(p1.y + b, 0.f);
        v1.x = fmaxf(p2.x + b, 0.f); v1.y = fmaxf(p2.y + b, 0.f);
        v1.z = fmaxf(p3.x + b, 0.f); v1.w = fmaxf(p3.y + b, 0.f);
        *(float4*)(sZg + (o0 + r) * 8)     = v0;
        *(float4*)(sZg + (o0 + r) * 8 + 4) = v1;
    }
}

// relu(acc + b2) -> global raw output + BN stat accumulation
__device__ __forceinline__ void epi2(const ull acc[16], const float* sB2,
                                     float* outrow, int o0, float* sStats) {
#pragma unroll
    for (int r = 0; r < 4; r++) {
        int o = o0 + r;
        float b = sB2[o];
        float2 p0 = upk(acc[r * 4 + 0]), p1 = upk(acc[r * 4 + 1]);
        float2 p2 = upk(acc[r * 4 + 2]), p3 = upk(acc[r * 4 + 3]);
        float f0 = fmaxf(p0.x + b, 0.f), f1 = fmaxf(p0.y + b, 0.f);
        float f2 = fmaxf(p1.x + b, 0.f), f3 = fmaxf(p1.y + b, 0.f);
        float f4 = fmaxf(p2.x + b, 0.f), f5 = fmaxf(p2.y + b, 0.f);
        float f6 = fmaxf(p3.x + b, 0.f), f7 = fmaxf(p3.y + b, 0.f);
        float4 v0 = {f0, f1, f2, f3}, v1 = {f4, f5, f6, f7};
        *(float4*)(outrow + o * 8)     = v0;
        *(float4*)(outrow + o * 8 + 4) = v1;
        float s = f0 + f1 + f2 + f3 + f4 + f5 + f6 + f7;
        float q = f0*f0 + f1*f1 + f2*f2 + f3*f3 + f4*f4 + f5*f5 + f6*f6 + f7*f7;
        s += __shfl_xor_sync(0xffffffffu, s, 16);
        q += __shfl_xor_sync(0xffffffffu, q, 16);
        if ((threadIdx.x & 16) == 0) {
            atomicAdd(&sStats[o], s);
            atomicAdd(&sStats[64 + o], q);
        }
    }
}

// ---------------- layer 0 (IN_DIM=1) ----------------
__global__ void __launch_bounds__(128) k_layer0(
    const float* __restrict__ x, const float* __restrict__ w10,
    const float* __restrict__ b1, const float* __restrict__ b2) {
    __shared__ float sZ[8 * FEAT];
    __shared__ float sZ0[64];
    __shared__ float sStats[128];
    __shared__ float sB2[64];
    int t = threadIdx.x;
    sStats[t] = 0.f;
    if (t < 64) sB2[t] = b2[t];
    int g = t >> 4, l = t & 15;
    int n = (blockIdx.x << 3) + g;
    if (l < 8) {
        float a = x[n * 8 + l];
        int rs = g_rowptr[n], re = g_rowptr[n + 1];
        for (int e = rs; e < re; e++) a += x[g_srce[e] * 8 + l];
        sZ0[g * 8 + l] = a;
    }
    __syncthreads();
    int o0 = l << 2;
    float zz[8];
#pragma unroll
    for (int m = 0; m < 8; m++) zz[m] = sZ0[g * 8 + m];
#pragma unroll
    for (int r = 0; r < 4; r++) {
        int o = o0 + r;
        float w = w10[o], b = b1[o];
        float4 v0, v1;
        v0.x = fmaxf(w * zz[0] + b, 0.f); v0.y = fmaxf(w * zz[1] + b, 0.f);
        v0.z = fmaxf(w * zz[2] + b, 0.f); v0.w = fmaxf(w * zz[3] + b, 0.f);
        v1.x = fmaxf(w * zz[4] + b, 0.f); v1.y = fmaxf(w * zz[5] + b, 0.f);
        v1.z = fmaxf(w * zz[6] + b, 0.f); v1.w = fmaxf(w * zz[7] + b, 0.f);
        *(float4*)(sZ + (g << 9) + o * 8)     = v0;
        *(float4*)(sZ + (g << 9) + o * 8 + 4) = v1;
    }
    __syncthreads();
    ull acc[16];
    gemm64(sZ + (g << 9), g_Wt2p + o0, acc);
    epi2(acc, sB2, g_bufA + (size_t)n * FEAT, o0, sStats);
    __syncthreads();
    atomicAdd(&g_stats[t], sStats[t]);
}

// ---------------- layers 1..4 (fused gather+affine + MLP + stats) ----------------
__global__ void __launch_bounds__(128) k_layer(
    int layer, const float* __restrict__ b1, const float* __restrict__ b2) {
    __shared__ float sZ[8 * FEAT];    // 16 KB, reused z -> y
    __shared__ float sStats[128];
    __shared__ float sAff[128];
    __shared__ float sB1[64], sB2[64];
    const float* in = (layer & 1) ? g_bufA : g_bufB;
    float*      out = (layer & 1) ? g_bufB : g_bufA;
    int t = threadIdx.x;
    sStats[t] = 0.f;
    sAff[t] = g_affine[(layer - 1) * 128 + t];
    if (t < 64) { sB1[t] = b1[t]; sB2[t] = b2[t]; }
    int g = t >> 4, l = t & 15;
    int n = (blockIdx.x << 3) + g;
    int rs = g_rowptr[n], re = g_rowptr[n + 1];
    float4 a[8];
    const float* base = in + (size_t)n * FEAT + l * 32;
#pragma unroll
    for (int j = 0; j < 8; j++) a[j] = *(const float4*)(base + j * 4);
    for (int e = rs; e < re; e++) {
        const float* sb = in + (size_t)g_srce[e] * FEAT + l * 32;
#pragma unroll
        for (int j = 0; j < 8; j++) {
            float4 v = *(const float4*)(sb + j * 4);
            a[j].x += v.x; a[j].y += v.y; a[j].z += v.z; a[j].w += v.w;
        }
    }
    // Thread l owns channels 4l..4l+3; a[j] covers channel 4l + (j>>1).
    float degp1 = (float)(re - rs + 1);
    float scr[4], shr[4];
#pragma unroll
    for (int r = 0; r < 4; r++) {
        scr[r] = sAff[4 * l + r];
        shr[r] = sAff[64 + 4 * l + r] * degp1;
    }
#pragma unroll
    for (int j = 0; j < 8; j++) {
        int cc = j >> 1;
        float sc = scr[cc], sh = shr[cc];
        a[j].x = sc * a[j].x + sh; a[j].y = sc * a[j].y + sh;
        a[j].z = sc * a[j].z + sh; a[j].w = sc * a[j].w + sh;
        *(float4*)(sZ + (g << 9) + l * 32 + j * 4) = a[j];
    }
    __syncthreads();
    int o0 = l << 2;
    ull acc[16];
    gemm64(sZ + (g << 9), g_Wt1p + ((layer - 1) << 12) + o0, acc);
    __syncthreads();
    epi1(acc, sB1, sZ + (g << 9), o0);
    __syncthreads();
    gemm64(sZ + (g << 9), g_Wt2p + (layer << 12) + o0, acc);
    epi2(acc, sB2, out + (size_t)n * FEAT, o0, sStats);
    __syncthreads();
    atomicAdd(&g_stats[layer * 128 + t], sStats[t]);
}

// ---------------- BN finalize: stats -> (scale, shift) ----------------
__global__ void k_finalize(int layer, const float* __restrict__ gamma,
                           const float* __restrict__ beta) {
    int c = threadIdx.x;  // 64 threads
    const float* st = g_stats + layer * 128;
    float inv = 1.0f / 160000.0f;
    float mean = st[c] * inv;
    float var = st[64 + c] * inv - mean * mean;
    float sc = gamma[c] * rsqrtf(var + 1e-5f);
    g_affine[layer * 128 + c]      = sc;
    g_affine[layer * 128 + 64 + c] = beta[c] - mean * sc;
}

// ---------------- pooling + head ----------------
__global__ void k_pool() {   // reads raw layer-4 output in g_bufA
    int t = threadIdx.x;     // 256 threads
    float a0 = 0.f, a1 = 0.f;
    for (int n = blockIdx.x; n < N_NODES; n += gridDim.x) {
        float2 v = *(const float2*)(g_bufA + (size_t)n * FEAT + t * 2);
        a0 += v.x; a1 += v.y;
    }
    atomicAdd(&g_pool[t * 2], a0);
    atomicAdd(&g_pool[t * 2 + 1], a1);
}

__global__ void k_final(const float* __restrict__ wout,
                        const float* __restrict__ bout, float* __restrict__ o) {
    int m = threadIdx.x;
    if (m < 8) {
        const float* aff = g_affine + 4 * 128;
        float acc = bout[0];
        for (int c = 0; c < 64; c++)
            acc += wout[c] * (aff[c] * g_pool[c * 8 + m] * (1.0f / N_NODES) + aff[64 + c]);
        o[m] = 1.0f / (1.0f + expf(-acc));
    }
}

// ---------------- launch ----------------
extern "C" void kernel_launch(void* const* d_in, const int* in_sizes, int n_in,
                              void* d_out, int out_size) {
    const float* x     = (const float*)d_in[0];
    const void*  ei    = d_in[1];
    // d_in[2] = batch (unused, all zeros)
    const float* w10   = (const float*)d_in[3];
    const float* w1    = (const float*)d_in[4];
    const float* b1    = (const float*)d_in[5];
    const float* w2    = (const float*)d_in[6];
    const float* b2    = (const float*)d_in[7];
    const float* gamma = (const float*)d_in[8];
    const float* beta  = (const float*)d_in[9];
    const float* wout  = (const float*)d_in[10];
    const float* bout  = (const float*)d_in[11];
    float* out = (float*)d_out;

    k_init<<<(N_NODES + 255) / 256, 256>>>();
    k_detect<<<1, 32>>>(ei);
    k_prep<<<(9 * 4096 + 255) / 256, 256>>>(w1, w2);
    k_hist<<<(N_EDGES + 255) / 256, 256>>>(ei);
    k_scan<<<1, 1024>>>();
    k_fill<<<(N_EDGES + 255) / 256, 256>>>(ei);

    k_layer0<<<N_NODES / 8, 128>>>(x, w10, b1, b2);
    k_finalize<<<1, 64>>>(0, gamma, beta);
    for (int i = 1; i <= 4; i++) {
        k_layer<<<N_NODES / 8, 128>>>(i, b1 + i * 64, b2 + i * 64);
        k_finalize<<<1, 64>>>(i, gamma + i * 64, beta + i * 64);
    }
    k_pool<<<256, 256>>>();
    k_final<<<1, 32>>>(wout, bout, out);
}

// round 3
// speedup vs baseline: 1.4903x; 1.4903x over previous
#include <cuda_runtime.h>
#include <cstdint>

// GIN: 5 layers, N=20000 nodes, E=320000 edges, HIDDEN=64, M=8.
//  - CSR build per launch (histogram + scan + fill).
//  - Per layer: k_gather (CSR gather + BN-affine -> z), k_mlp (2 GEMMs via
//    fma.rn.f32x2 + relu + BN-stat accumulation), k_finalize (stats->affine).
//  - h kept in-place in g_bufA; z in g_bufB.

#define N_NODES 20000
#define N_EDGES 320000
#define HID 64
#define MDIM 8
#define FEAT (HID*MDIM)   // 512 floats per node

typedef unsigned long long ull;

// ---------------- device scratch ----------------
__device__ float g_bufA[N_NODES * FEAT];   // h (in place across layers)
__device__ float g_bufB[N_NODES * FEAT];   // z scratch
__device__ int   g_rowptr[N_NODES + 1];
__device__ int   g_count[N_NODES];
__device__ int   g_fill[N_NODES];
__device__ int   g_srce[N_EDGES];
__device__ float g_stats[5 * 128];         // per layer: sum[64], sumsq[64]
__device__ float g_affine[5 * 128];        // per layer: scale[64], shift[64]
__device__ ull   g_Wt1p[4 * 4096];         // W1 layers 1..4, [c][o], (w,w) pairs
__device__ ull   g_Wt2p[5 * 4096];         // W2 layers 0..4, [c][o], (w,w) pairs
__device__ float g_pool[FEAT];
__device__ int   g_is64;

// ---------------- f32x2 helpers ----------------
__device__ __forceinline__ ull pk2(float a, float b) {
    ull r; asm("mov.b64 %0, {%1, %2};" : "=l"(r) : "f"(a), "f"(b)); return r;
}
__device__ __forceinline__ float2 upk(ull v) {
    float2 r; asm("mov.b64 {%0, %1}, %2;" : "=f"(r.x), "=f"(r.y) : "l"(v)); return r;
}
__device__ __forceinline__ void fma2(ull& a, ull b, ull c) {
    asm("fma.rn.f32x2 %0, %1, %2, %0;" : "+l"(a) : "l"(b), "l"(c));
}

// ---------------- setup kernels ----------------
__global__ void k_init() {
    int i = blockIdx.x * blockDim.x + threadIdx.x;
    if (i < N_NODES) { g_count[i] = 0; g_fill[i] = 0; }
    if (i < 5 * 128) g_stats[i] = 0.f;
    if (i < FEAT)    g_pool[i] = 0.f;
}

__global__ void k_detect(const void* ei) {
    if (threadIdx.x == 0 && blockIdx.x == 0) {
        const ull* p = (const ull*)ei;
        int is64 = 1;
        for (int j = 0; j < 64; j++)
            if (p[j] >= (ull)N_NODES) is64 = 0;
        g_is64 = is64;
    }
}

__device__ __forceinline__ int edge_at(const void* ei, int idx) {
    return g_is64 ? (int)((const long long*)ei)[idx] : ((const int*)ei)[idx];
}

__global__ void k_hist(const void* ei) {
    int e = blockIdx.x * blockDim.x + threadIdx.x;
    if (e >= N_EDGES) return;
    atomicAdd(&g_count[edge_at(ei, N_EDGES + e)], 1);
}

__global__ void k_scan() {   // 1 block, 1024 threads, exclusive prefix over 20000
    __shared__ int s[1024];
    const int CH = 20;
    int t = threadIdx.x;
    int base = t * CH;
    int vals[CH];
    int local = 0;
#pragma unroll
    for (int j = 0; j < CH; j++) {
        int i = base + j;
        int v = (i < N_NODES) ? g_count[i] : 0;
        vals[j] = local; local += v;
    }
    s[t] = local;
    __syncthreads();
    for (int off = 1; off < 1024; off <<= 1) {
        int v = s[t];
        int add = (t >= off) ? s[t - off] : 0;
        __syncthreads();
        s[t] = v + add;
        __syncthreads();
    }
    int bb = (t == 0) ? 0 : s[t - 1];
#pragma unroll
    for (int j = 0; j < CH; j++) {
        int i = base + j;
        if (i < N_NODES) g_rowptr[i] = bb + vals[j];
    }
    if (t == 1023) g_rowptr[N_NODES] = s[1023];
}

__global__ void k_fill(const void* ei) {
    int e = blockIdx.x * blockDim.x + threadIdx.x;
    if (e >= N_EDGES) return;
    int srcv = edge_at(ei, e);
    int d    = edge_at(ei, N_EDGES + e);
    int pos  = g_rowptr[d] + atomicAdd(&g_fill[d], 1);
    g_srce[pos] = srcv;
}

// transpose + duplicate weights into (w,w) f32x2 pairs, layout [mat][c][o]
__global__ void k_prep(const float* __restrict__ w1, const float* __restrict__ w2) {
    int idx = blockIdx.x * blockDim.x + threadIdx.x;
    if (idx < 4 * 4096) {
        int mat = idx >> 12, r = idx & 4095, o = r >> 6, c = r & 63;
        float v = w1[idx];
        g_Wt1p[(mat << 12) + (c << 6) + o] = pk2(v, v);
    } else if (idx < 9 * 4096) {
        int j = idx - 4 * 4096;
        int mat = j >> 12, r = j & 4095, o = r >> 6, c = r & 63;
        float v = w2[j];
        g_Wt2p[(mat << 12) + (c << 6) + o] = pk2(v, v);
    }
}

// ---------------- GEMM core: out[o0..o0+3][m0..7] over K=64 ----------------
__device__ __forceinline__ void gemm64(const float* sIn, const ull* __restrict__ Wp,
                                       ull acc[16]) {
#pragma unroll
    for (int i = 0; i < 16; i++) acc[i] = 0ULL;
#pragma unroll 8
    for (int c = 0; c < 64; c++) {
        ulonglong2 wa = *(const ulonglong2*)(Wp + (c << 6));
        ulonglong2 wb = *(const ulonglong2*)(Wp + (c << 6) + 2);
        ulonglong2 za = *(const ulonglong2*)(sIn + (c << 3));
        ulonglong2 zb = *(const ulonglong2*)(sIn + (c << 3) + 4);
        ull w0 = wa.x, w1 = wa.y, w2 = wb.x, w3 = wb.y;
        ull z0 = za.x, z1 = za.y, z2 = zb.x, z3 = zb.y;
        fma2(acc[0],  w0, z0); fma2(acc[1],  w0, z1); fma2(acc[2],  w0, z2); fma2(acc[3],  w0, z3);
        fma2(acc[4],  w1, z0); fma2(acc[5],  w1, z1); fma2(acc[6],  w1, z2); fma2(acc[7],  w1, z3);
        fma2(acc[8],  w2, z0); fma2(acc[9],  w2, z1); fma2(acc[10], w2, z2); fma2(acc[11], w2, z3);
        fma2(acc[12], w3, z0); fma2(acc[13], w3, z1); fma2(acc[14], w3, z2); fma2(acc[15], w3, z3);
    }
}

// relu(acc + b1) -> shared
__device__ __forceinline__ void epi1(const ull acc[16], const float* sB1,
                                     float* sZg, int o0) {
#pragma unroll
    for (int r = 0; r < 4; r++) {
        float b = sB1[o0 + r];
        float2 p0 = upk(acc[r * 4 + 0]), p1 = upk(acc[r * 4 + 1]);
        float2 p2 = upk(acc[r * 4 + 2]), p3 = upk(acc[r * 4 + 3]);
        float4 v0, v1;
        v0.x = fmaxf(p0.x + b, 0.f); v0.y = fmaxf(p0.y + b, 0.f);
        v0.z = fmaxf(p1.x + b, 0.f); v0.w = fmaxf(p1.y + b, 0.f);
        v1.x = fmaxf(p2.x + b, 0.f); v1.y = fmaxf(p2.y + b, 0.f);
        v1.z = fmaxf(p3.x + b, 0.f); v1.w = fmaxf(p3.y + b, 0.f);
        *(float4*)(sZg + (o0 + r) * 8)     = v0;
        *(float4*)(sZg + (o0 + r) * 8 + 4) = v1;
    }
}

// relu(acc + b2) -> global raw output + BN stat accumulation
__device__ __forceinline__ void epi2(const ull acc[16], const float* sB2,
                                     float* outrow, int o0, float* sStats) {
#pragma unroll
    for (int r = 0; r < 4; r++) {
        int o = o0 + r;
        float b = sB2[o];
        float2 p0 = upk(acc[r * 4 + 0]), p1 = upk(acc[r * 4 + 1]);
        float2 p2 = upk(acc[r * 4 + 2]), p3 = upk(acc[r * 4 + 3]);
        float f0 = fmaxf(p0.x + b, 0.f), f1 = fmaxf(p0.y + b, 0.f);
        float f2 = fmaxf(p1.x + b, 0.f), f3 = fmaxf(p1.y + b, 0.f);
        float f4 = fmaxf(p2.x + b, 0.f), f5 = fmaxf(p2.y + b, 0.f);
        float f6 = fmaxf(p3.x + b, 0.f), f7 = fmaxf(p3.y + b, 0.f);
        float4 v0 = {f0, f1, f2, f3}, v1 = {f4, f5, f6, f7};
        *(float4*)(outrow + o * 8)     = v0;
        *(float4*)(outrow + o * 8 + 4) = v1;
        float s = f0 + f1 + f2 + f3 + f4 + f5 + f6 + f7;
        float q = f0*f0 + f1*f1 + f2*f2 + f3*f3 + f4*f4 + f5*f5 + f6*f6 + f7*f7;
        s += __shfl_xor_sync(0xffffffffu, s, 16);
        q += __shfl_xor_sync(0xffffffffu, q, 16);
        if ((threadIdx.x & 16) == 0) {
            atomicAdd(&sStats[o], s);
            atomicAdd(&sStats[64 + o], q);
        }
    }
}

// ---------------- layer 0 (IN_DIM=1) ----------------
__global__ void __launch_bounds__(128) k_layer0(
    const float* __restrict__ x, const float* __restrict__ w10,
    const float* __restrict__ b1, const float* __restrict__ b2) {
    __shared__ float sZ[8 * FEAT];
    __shared__ float sZ0[64];
    __shared__ float sStats[128];
    __shared__ float sB2[64];
    int t = threadIdx.x;
    sStats[t] = 0.f;
    if (t < 64) sB2[t] = b2[t];
    int g = t >> 4, l = t & 15;
    int n = (blockIdx.x << 3) + g;
    if (l < 8) {
        float a = x[n * 8 + l];
        int rs = g_rowptr[n], re = g_rowptr[n + 1];
        for (int e = rs; e < re; e++) a += x[g_srce[e] * 8 + l];
        sZ0[g * 8 + l] = a;
    }
    __syncthreads();
    int o0 = l << 2;
    float zz[8];
#pragma unroll
    for (int m = 0; m < 8; m++) zz[m] = sZ0[g * 8 + m];
#pragma unroll
    for (int r = 0; r < 4; r++) {
        int o = o0 + r;
        float w = w10[o], b = b1[o];
        float4 v0, v1;
        v0.x = fmaxf(w * zz[0] + b, 0.f); v0.y = fmaxf(w * zz[1] + b, 0.f);
        v0.z = fmaxf(w * zz[2] + b, 0.f); v0.w = fmaxf(w * zz[3] + b, 0.f);
        v1.x = fmaxf(w * zz[4] + b, 0.f); v1.y = fmaxf(w * zz[5] + b, 0.f);
        v1.z = fmaxf(w * zz[6] + b, 0.f); v1.w = fmaxf(w * zz[7] + b, 0.f);
        *(float4*)(sZ + (g << 9) + o * 8)     = v0;
        *(float4*)(sZ + (g << 9) + o * 8 + 4) = v1;
    }
    __syncthreads();
    ull acc[16];
    gemm64(sZ + (g << 9), g_Wt2p + o0, acc);
    epi2(acc, sB2, g_bufA + (size_t)n * FEAT, o0, sStats);
    __syncthreads();
    atomicAdd(&g_stats[t], sStats[t]);
}

// ---------------- gather (layers 1..4): CSR gather + BN affine -> z ----------------
// 64 threads per node, one channel per thread (8 floats = 2 float4).
__global__ void __launch_bounds__(256) k_gather(int layer) {
    const float* __restrict__ in = g_bufA;
    float* __restrict__ z = g_bufB;
    int t = threadIdx.x;
    int grp = t >> 6;          // node within block: 0..3
    int l = t & 63;            // channel
    int n = (blockIdx.x << 2) + grp;
    int rs = g_rowptr[n], re = g_rowptr[n + 1];
    float sc = g_affine[(layer - 1) * 128 + l];
    float sh = g_affine[(layer - 1) * 128 + 64 + l];
    const float* base = in + (size_t)n * FEAT + (l << 3);
    float4 a0 = *(const float4*)base;
    float4 a1 = *(const float4*)(base + 4);
    float4 c0 = {0.f, 0.f, 0.f, 0.f}, c1 = {0.f, 0.f, 0.f, 0.f};
    int e = rs;
    for (; e + 2 <= re; e += 2) {
        const float* p0 = in + (size_t)g_srce[e]     * FEAT + (l << 3);
        const float* p1 = in + (size_t)g_srce[e + 1] * FEAT + (l << 3);
        float4 v0 = *(const float4*)p0, v1 = *(const float4*)(p0 + 4);
        float4 u0 = *(const float4*)p1, u1 = *(const float4*)(p1 + 4);
        a0.x += v0.x; a0.y += v0.y; a0.z += v0.z; a0.w += v0.w;
        a1.x += v1.x; a1.y += v1.y; a1.z += v1.z; a1.w += v1.w;
        c0.x += u0.x; c0.y += u0.y; c0.z += u0.z; c0.w += u0.w;
        c1.x += u1.x; c1.y += u1.y; c1.z += u1.z; c1.w += u1.w;
    }
    if (e < re) {
        const float* p0 = in + (size_t)g_srce[e] * FEAT + (l << 3);
        float4 v0 = *(const float4*)p0, v1 = *(const float4*)(p0 + 4);
        a0.x += v0.x; a0.y += v0.y; a0.z += v0.z; a0.w += v0.w;
        a1.x += v1.x; a1.y += v1.y; a1.z += v1.z; a1.w += v1.w;
    }
    a0.x += c0.x; a0.y += c0.y; a0.z += c0.z; a0.w += c0.w;
    a1.x += c1.x; a1.y += c1.y; a1.z += c1.z; a1.w += c1.w;
    float shd = sh * (float)(re - rs + 1);
    a0.x = sc * a0.x + shd; a0.y = sc * a0.y + shd;
    a0.z = sc * a0.z + shd; a0.w = sc * a0.w + shd;
    a1.x = sc * a1.x + shd; a1.y = sc * a1.y + shd;
    a1.z = sc * a1.z + shd; a1.w = sc * a1.w + shd;
    float* zb = z + (size_t)n * FEAT + (l << 3);
    *(float4*)zb       = a0;
    *(float4*)(zb + 4) = a1;
}

// ---------------- MLP (layers 1..4): z -> 2 GEMMs -> h (+BN stats) ----------------
__global__ void __launch_bounds__(128) k_mlp(
    int layer, const float* __restrict__ b1, const float* __restrict__ b2) {
    __shared__ float sZ[8 * FEAT];    // 16 KB, reused z -> y
    __shared__ float sStats[128];
    __shared__ float sB1[64], sB2[64];
    const float* __restrict__ z = g_bufB;
    float* __restrict__ out = g_bufA;
    int t = threadIdx.x;
    sStats[t] = 0.f;
    if (t < 64) { sB1[t] = b1[t]; sB2[t] = b2[t]; }
    // cooperative coalesced load of 8 node rows (4096 floats = 1024 float4)
    const float4* src = (const float4*)(z + (size_t)(blockIdx.x << 3) * FEAT);
    float4* dst = (float4*)sZ;
#pragma unroll
    for (int j = 0; j < 8; j++) dst[t + 128 * j] = src[t + 128 * j];
    __syncthreads();
    int g = t >> 4, l = t & 15, o0 = l << 2;
    int n = (blockIdx.x << 3) + g;
    ull acc[16];
    gemm64(sZ + (g << 9), g_Wt1p + ((layer - 1) << 12) + o0, acc);
    __syncthreads();
    epi1(acc, sB1, sZ + (g << 9), o0);
    __syncthreads();
    gemm64(sZ + (g << 9), g_Wt2p + (layer << 12) + o0, acc);
    epi2(acc, sB2, out + (size_t)n * FEAT, o0, sStats);
    __syncthreads();
    atomicAdd(&g_stats[layer * 128 + t], sStats[t]);
}

// ---------------- BN finalize: stats -> (scale, shift) ----------------
__global__ void k_finalize(int layer, const float* __restrict__ gamma,
                           const float* __restrict__ beta) {
    int c = threadIdx.x;  // 64 threads
    const float* st = g_stats + layer * 128;
    float inv = 1.0f / 160000.0f;
    float mean = st[c] * inv;
    float var = st[64 + c] * inv - mean * mean;
    float sc = gamma[c] * rsqrtf(var + 1e-5f);
    g_affine[layer * 128 + c]      = sc;
    g_affine[layer * 128 + 64 + c] = beta[c] - mean * sc;
}

// ---------------- pooling + head ----------------
__global__ void k_pool() {   // reads raw layer-4 output in g_bufA
    int t = threadIdx.x;     // 256 threads
    float a0 = 0.f, a1 = 0.f;
    for (int n = blockIdx.x; n < N_NODES; n += gridDim.x) {
        float2 v = *(const float2*)(g_bufA + (size_t)n * FEAT + t * 2);
        a0 += v.x; a1 += v.y;
    }
    atomicAdd(&g_pool[t * 2], a0);
    atomicAdd(&g_pool[t * 2 + 1], a1);
}

__global__ void k_final(const float* __restrict__ wout,
                        const float* __restrict__ bout, float* __restrict__ o) {
    int m = threadIdx.x;
    if (m < 8) {
        const float* aff = g_affine + 4 * 128;
        float acc = bout[0];
        for (int c = 0; c < 64; c++)
            acc += wout[c] * (aff[c] * g_pool[c * 8 + m] * (1.0f / N_NODES) + aff[64 + c]);
        o[m] = 1.0f / (1.0f + expf(-acc));
    }
}

// ---------------- launch ----------------
extern "C" void kernel_launch(void* const* d_in, const int* in_sizes, int n_in,
                              void* d_out, int out_size) {
    const float* x     = (const float*)d_in[0];
    const void*  ei    = d_in[1];
    // d_in[2] = batch (unused, all zeros)
    const float* w10   = (const float*)d_in[3];
    const float* w1    = (const float*)d_in[4];
    const float* b1    = (const float*)d_in[5];
    const float* w2    = (const float*)d_in[6];
    const float* b2    = (const float*)d_in[7];
    const float* gamma = (const float*)d_in[8];
    const float* beta  = (const float*)d_in[9];
    const float* wout  = (const float*)d_in[10];
    const float* bout  = (const float*)d_in[11];
    float* out = (float*)d_out;

    k_init<<<(N_NODES + 255) / 256, 256>>>();
    k_detect<<<1, 32>>>(ei);
    k_prep<<<(9 * 4096 + 255) / 256, 256>>>(w1, w2);
    k_hist<<<(N_EDGES + 255) / 256, 256>>>(ei);
    k_scan<<<1, 1024>>>();
    k_fill<<<(N_EDGES + 255) / 256, 256>>>(ei);

    k_layer0<<<N_NODES / 8, 128>>>(x, w10, b1, b2);
    k_finalize<<<1, 64>>>(0, gamma, beta);
    for (int i = 1; i <= 4; i++) {
        k_gather<<<N_NODES / 4, 256>>>(i);
        k_mlp<<<N_NODES / 8, 128>>>(i, b1 + i * 64, b2 + i * 64);
        k_finalize<<<1, 64>>>(i, gamma + i * 64, beta + i * 64);
    }
    k_pool<<<256, 256>>>();
    k_final<<<1, 32>>>(wout, bout, out);
}

// round 5
// speedup vs baseline: 1.6159x; 1.0843x over previous
#include <cuda_runtime.h>
#include <cuda_fp16.h>
#include <cstdint>

// GIN: 5 layers, N=20000 nodes, E=320000 edges, HIDDEN=64, M=8.
//  - CSR build per launch (histogram + scan + fill).
//  - h kept fp32 in g_bufA + fp16 mirror in g_hbuf (written in MLP epilogue).
//  - k_gather reads the fp16 mirror (half the L2 bytes), accumulates fp32,
//    applies BN affine, writes z fp32. k_mlp: 2 GEMMs via fma.rn.f32x2.
//  - BN folded to per-channel affine; finalize kernel per layer.

#define N_NODES 20000
#define N_EDGES 320000
#define HID 64
#define MDIM 8
#define FEAT (HID*MDIM)   // 512 floats per node

typedef unsigned long long ull;

// ---------------- device scratch ----------------
__device__ float  g_bufA[N_NODES * FEAT];   // h fp32 (in place across layers)
__device__ float  g_bufB[N_NODES * FEAT];   // z scratch
__device__ __half g_hbuf[N_NODES * FEAT];   // h fp16 mirror (gather source)
__device__ int    g_rowptr[N_NODES + 1];
__device__ int    g_count[N_NODES];
__device__ int    g_fill[N_NODES];
__device__ int    g_srce[N_EDGES];
__device__ float  g_stats[5 * 128];         // per layer: sum[64], sumsq[64]
__device__ float  g_affine[5 * 128];        // per layer: scale[64], shift[64]
__device__ ull    g_Wt1p[4 * 4096];         // W1 layers 1..4, [c][o], (w,w) pairs
__device__ ull    g_Wt2p[5 * 4096];         // W2 layers 0..4, [c][o], (w,w) pairs
__device__ float  g_pool[FEAT];
__device__ int    g_is64;

// ---------------- f32x2 helpers ----------------
__device__ __forceinline__ ull pk2(float a, float b) {
    ull r; asm("mov.b64 %0, {%1, %2};" : "=l"(r) : "f"(a), "f"(b)); return r;
}
__device__ __forceinline__ float2 upk(ull v) {
    float2 r; asm("mov.b64 {%0, %1}, %2;" : "=f"(r.x), "=f"(r.y) : "l"(v)); return r;
}
__device__ __forceinline__ void fma2(ull& a, ull b, ull c) {
    asm("fma.rn.f32x2 %0, %1, %2, %0;" : "+l"(a) : "l"(b), "l"(c));
}

// ---------------- setup kernels ----------------
__global__ void k_init() {
    int i = blockIdx.x * blockDim.x + threadIdx.x;
    if (i < N_NODES) { g_count[i] = 0; g_fill[i] = 0; }
    if (i < 5 * 128) g_stats[i] = 0.f;
    if (i < FEAT)    g_pool[i] = 0.f;
}

__global__ void k_detect(const void* ei) {
    if (threadIdx.x == 0 && blockIdx.x == 0) {
        const ull* p = (const ull*)ei;
        int is64 = 1;
        for (int j = 0; j < 64; j++)
            if (p[j] >= (ull)N_NODES) is64 = 0;
        g_is64 = is64;
    }
}

__device__ __forceinline__ int edge_at(const void* ei, int idx) {
    return g_is64 ? (int)((const long long*)ei)[idx] : ((const int*)ei)[idx];
}

__global__ void k_hist(const void* ei) {
    int e = blockIdx.x * blockDim.x + threadIdx.x;
    if (e >= N_EDGES) return;
    atomicAdd(&g_count[edge_at(ei, N_EDGES + e)], 1);
}

__global__ void k_scan() {   // 1 block, 1024 threads, exclusive prefix over 20000
    __shared__ int s[1024];
    const int CH = 20;
    int t = threadIdx.x;
    int base = t * CH;
    int vals[CH];
    int local = 0;
#pragma unroll
    for (int j = 0; j < CH; j++) {
        int i = base + j;
        int v = (i < N_NODES) ? g_count[i] : 0;
        vals[j] = local; local += v;
    }
    s[t] = local;
    __syncthreads();
    for (int off = 1; off < 1024; off <<= 1) {
        int v = s[t];
        int add = (t >= off) ? s[t - off] : 0;
        __syncthreads();
        s[t] = v + add;
        __syncthreads();
    }
    int bb = (t == 0) ? 0 : s[t - 1];
#pragma unroll
    for (int j = 0; j < CH; j++) {
        int i = base + j;
        if (i < N_NODES) g_rowptr[i] = bb + vals[j];
    }
    if (t == 1023) g_rowptr[N_NODES] = s[1023];
}

__global__ void k_fill(const void* ei) {
    int e = blockIdx.x * blockDim.x + threadIdx.x;
    if (e >= N_EDGES) return;
    int srcv = edge_at(ei, e);
    int d    = edge_at(ei, N_EDGES + e);
    int pos  = g_rowptr[d] + atomicAdd(&g_fill[d], 1);
    g_srce[pos] = srcv;
}

// transpose + duplicate weights into (w,w) f32x2 pairs, layout [mat][c][o]
__global__ void k_prep(const float* __restrict__ w1, const float* __restrict__ w2) {
    int idx = blockIdx.x * blockDim.x + threadIdx.x;
    if (idx < 4 * 4096) {
        int mat = idx >> 12, r = idx & 4095, o = r >> 6, c = r & 63;
        float v = w1[idx];
        g_Wt1p[(mat << 12) + (c << 6) + o] = pk2(v, v);
    } else if (idx < 9 * 4096) {
        int j = idx - 4 * 4096;
        int mat = j >> 12, r = j & 4095, o = r >> 6, c = r & 63;
        float v = w2[j];
        g_Wt2p[(mat << 12) + (c << 6) + o] = pk2(v, v);
    }
}

// ---------------- GEMM core: out[o0..o0+3][m0..7] over K=64 ----------------
__device__ __forceinline__ void gemm64(const float* sIn, const ull* __restrict__ Wp,
                                       ull acc[16]) {
#pragma unroll
    for (int i = 0; i < 16; i++) acc[i] = 0ULL;
#pragma unroll 8
    for (int c = 0; c < 64; c++) {
        ulonglong2 wa = *(const ulonglong2*)(Wp + (c << 6));
        ulonglong2 wb = *(const ulonglong2*)(Wp + (c << 6) + 2);
        ulonglong2 za = *(const ulonglong2*)(sIn + (c << 3));
        ulonglong2 zb = *(const ulonglong2*)(sIn + (c << 3) + 4);
        ull w0 = wa.x, w1 = wa.y, w2 = wb.x, w3 = wb.y;
        ull z0 = za.x, z1 = za.y, z2 = zb.x, z3 = zb.y;
        fma2(acc[0],  w0, z0); fma2(acc[1],  w0, z1); fma2(acc[2],  w0, z2); fma2(acc[3],  w0, z3);
        fma2(acc[4],  w1, z0); fma2(acc[5],  w1, z1); fma2(acc[6],  w1, z2); fma2(acc[7],  w1, z3);
        fma2(acc[8],  w2, z0); fma2(acc[9],  w2, z1); fma2(acc[10], w2, z2); fma2(acc[11], w2, z3);
        fma2(acc[12], w3, z0); fma2(acc[13], w3, z1); fma2(acc[14], w3, z2); fma2(acc[15], w3, z3);
    }
}

// relu(acc + b1) -> shared
__device__ __forceinline__ void epi1(const ull acc[16], const float* sB1,
                                     float* sZg, int o0) {
#pragma unroll
    for (int r = 0; r < 4; r++) {
        float b = sB1[o0 + r];
        float2 p0 = upk(acc[r * 4 + 0]), p1 = upk(acc[r * 4 + 1]);
        float2 p2 = upk(acc[r * 4 + 2]), p3 = upk(acc[r * 4 + 3]);
        float4 v0, v1;
        v0.x = fmaxf(p0.x + b, 0.f); v0.y = fmaxf(p0.y + b, 0.f);
        v0.z = fmaxf(p1.x + b, 0.f); v0.w = fmaxf(p1.y + b, 0.f);
        v1.x = fmaxf(p2.x + b, 0.f); v1.y = fmaxf(p2.y + b, 0.f);
        v1.z = fmaxf(p3.x + b, 0.f); v1.w = fmaxf(p3.y + b, 0.f);
        *(float4*)(sZg + (o0 + r) * 8)     = v0;
        *(float4*)(sZg + (o0 + r) * 8 + 4) = v1;
    }
}

// relu(acc + b2) -> global fp32 + fp16 mirror + BN stat accumulation
__device__ __forceinline__ void epi2(const ull acc[16], const float* sB2,
                                     float* outrow, __half* outh,
                                     int o0, float* sStats) {
#pragma unroll
    for (int r = 0; r < 4; r++) {
        int o = o0 + r;
        float b = sB2[o];
        float2 p0 = upk(acc[r * 4 + 0]), p1 = upk(acc[r * 4 + 1]);
        float2 p2 = upk(acc[r * 4 + 2]), p3 = upk(acc[r * 4 + 3]);
        float f0 = fmaxf(p0.x + b, 0.f), f1 = fmaxf(p0.y + b, 0.f);
        float f2 = fmaxf(p1.x + b, 0.f), f3 = fmaxf(p1.y + b, 0.f);
        float f4 = fmaxf(p2.x + b, 0.f), f5 = fmaxf(p2.y + b, 0.f);
        float f6 = fmaxf(p3.x + b, 0.f), f7 = fmaxf(p3.y + b, 0.f);
        float4 v0 = {f0, f1, f2, f3}, v1 = {f4, f5, f6, f7};
        *(float4*)(outrow + o * 8)     = v0;
        *(float4*)(outrow + o * 8 + 4) = v1;
        // fp16 mirror: 8 halves = 16B
        __half2 h0 = __floats2half2_rn(f0, f1);
        __half2 h1 = __floats2half2_rn(f2, f3);
        __half2 h2 = __floats2half2_rn(f4, f5);
        __half2 h3 = __floats2half2_rn(f6, f7);
        uint4 hv;
        hv.x = *(unsigned*)&h0; hv.y = *(unsigned*)&h1;
        hv.z = *(unsigned*)&h2; hv.w = *(unsigned*)&h3;
        *(uint4*)(outh + o * 8) = hv;
        float s = f0 + f1 + f2 + f3 + f4 + f5 + f6 + f7;
        float q = f0*f0 + f1*f1 + f2*f2 + f3*f3 + f4*f4 + f5*f5 + f6*f6 + f7*f7;
        s += __shfl_xor_sync(0xffffffffu, s, 16);
        q += __shfl_xor_sync(0xffffffffu, q, 16);
        if ((threadIdx.x & 16) == 0) {
            atomicAdd(&sStats[o], s);
            atomicAdd(&sStats[64 + o], q);
        }
    }
}

// ---------------- layer 0 (IN_DIM=1) ----------------
__global__ void __launch_bounds__(128) k_layer0(
    const float* __restrict__ x, const float* __restrict__ w10,
    const float* __restrict__ b1, const float* __restrict__ b2) {
    __shared__ float sZ[8 * FEAT];
    __shared__ float sZ0[64];
    __shared__ float sStats[128];
    __shared__ float sB2[64];
    int t = threadIdx.x;
    sStats[t] = 0.f;
    if (t < 64) sB2[t] = b2[t];
    int g = t >> 4, l = t & 15;
    int n = (blockIdx.x << 3) + g;
    if (l < 8) {
        float a = x[n * 8 + l];
        int rs = g_rowptr[n], re = g_rowptr[n + 1];
        for (int e = rs; e < re; e++) a += x[g_srce[e] * 8 + l];
        sZ0[g * 8 + l] = a;
    }
    __syncthreads();
    int o0 = l << 2;
    float zz[8];
#pragma unroll
    for (int m = 0; m < 8; m++) zz[m] = sZ0[g * 8 + m];
#pragma unroll
    for (int r = 0; r < 4; r++) {
        int o = o0 + r;
        float w = w10[o], b = b1[o];
        float4 v0, v1;
        v0.x = fmaxf(w * zz[0] + b, 0.f); v0.y = fmaxf(w * zz[1] + b, 0.f);
        v0.z = fmaxf(w * zz[2] + b, 0.f); v0.w = fmaxf(w * zz[3] + b, 0.f);
        v1.x = fmaxf(w * zz[4] + b, 0.f); v1.y = fmaxf(w * zz[5] + b, 0.f);
        v1.z = fmaxf(w * zz[6] + b, 0.f); v1.w = fmaxf(w * zz[7] + b, 0.f);
        *(float4*)(sZ + (g << 9) + o * 8)     = v0;
        *(float4*)(sZ + (g << 9) + o * 8 + 4) = v1;
    }
    __syncthreads();
    ull acc[16];
    gemm64(sZ + (g << 9), g_Wt2p + o0, acc);
    epi2(acc, sB2, g_bufA + (size_t)n * FEAT, g_hbuf + (size_t)n * FEAT, o0, sStats);
    __syncthreads();
    atomicAdd(&g_stats[t], sStats[t]);
}

// ---------------- gather (layers 1..4): fp16 CSR gather + BN affine -> z ----------------
// 64 threads per node, one channel per thread (8 halves = 16B = 1 LDG.128).
__device__ __forceinline__ void acc8(float a[8], uint4 v) {
    float2 p;
    p = __half22float2(*(const __half2*)&v.x); a[0] += p.x; a[1] += p.y;
    p = __half22float2(*(const __half2*)&v.y); a[2] += p.x; a[3] += p.y;
    p = __half22float2(*(const __half2*)&v.z); a[4] += p.x; a[5] += p.y;
    p = __half22float2(*(const __half2*)&v.w); a[6] += p.x; a[7] += p.y;
}

__global__ void __launch_bounds__(256) k_gather(int layer) {
    const uint4* __restrict__ in = (const uint4*)g_hbuf;  // 64 uint4 per node row
    float* __restrict__ z = g_bufB;
    int t = threadIdx.x;
    int grp = t >> 6;          // node within block: 0..3
    int l = t & 63;            // channel
    int n = (blockIdx.x << 2) + grp;
    int rs = g_rowptr[n], re = g_rowptr[n + 1];
    float sc = g_affine[(layer - 1) * 128 + l];
    float sh = g_affine[(layer - 1) * 128 + 64 + l];
    float a[8] = {0,0,0,0,0,0,0,0}, b[8] = {0,0,0,0,0,0,0,0};
    acc8(a, in[(size_t)n * 64 + l]);   // self
    int e = rs;
    for (; e + 2 <= re; e += 2) {
        uint4 v0 = in[(size_t)g_srce[e]     * 64 + l];
        uint4 v1 = in[(size_t)g_srce[e + 1] * 64 + l];
        acc8(a, v0);
        acc8(b, v1);
    }
    if (e < re) acc8(a, in[(size_t)g_srce[e] * 64 + l]);
    float shd = sh * (float)(re - rs + 1);
    float4 o0, o1;
    o0.x = sc * (a[0] + b[0]) + shd; o0.y = sc * (a[1] + b[1]) + shd;
    o0.z = sc * (a[2] + b[2]) + shd; o0.w = sc * (a[3] + b[3]) + shd;
    o1.x = sc * (a[4] + b[4]) + shd; o1.y = sc * (a[5] + b[5]) + shd;
    o1.z = sc * (a[6] + b[6]) + shd; o1.w = sc * (a[7] + b[7]) + shd;
    float* zb = z + (size_t)n * FEAT + (l << 3);
    *(float4*)zb       = o0;
    *(float4*)(zb + 4) = o1;
}

// ---------------- MLP (layers 1..4): z -> 2 GEMMs -> h (+BN stats) ----------------
__global__ void __launch_bounds__(128) k_mlp(
    int layer, const float* __restrict__ b1, const float* __restrict__ b2) {
    __shared__ float sZ[8 * FEAT];    // 16 KB, reused z -> y
    __shared__ float sStats[128];
    __shared__ float sB1[64], sB2[64];
    const float* __restrict__ z = g_bufB;
    int t = threadIdx.x;
    sStats[t] = 0.f;
    if (t < 64) { sB1[t] = b1[t]; sB2[t] = b2[t]; }
    const float4* src = (const float4*)(z + (size_t)(blockIdx.x << 3) * FEAT);
    float4* dst = (float4*)sZ;
#pragma unroll
    for (int j = 0; j < 8; j++) dst[t + 128 * j] = src[t + 128 * j];
    __syncthreads();
    int g = t >> 4, l = t & 15, o0 = l << 2;
    int n = (blockIdx.x << 3) + g;
    ull acc[16];
    gemm64(sZ + (g << 9), g_Wt1p + ((layer - 1) << 12) + o0, acc);
    __syncthreads();
    epi1(acc, sB1, sZ + (g << 9), o0);
    __syncthreads();
    gemm64(sZ + (g << 9), g_Wt2p + (layer << 12) + o0, acc);
    epi2(acc, sB2, g_bufA + (size_t)n * FEAT, g_hbuf + (size_t)n * FEAT, o0, sStats);
    __syncthreads();
    atomicAdd(&g_stats[layer * 128 + t], sStats[t]);
}

// ---------------- BN finalize: stats -> (scale, shift) ----------------
__global__ void k_finalize(int layer, const float* __restrict__ gamma,
                           const float* __restrict__ beta) {
    int c = threadIdx.x;  // 64 threads
    const float* st = g_stats + layer * 128;
    float inv = 1.0f / 160000.0f;
    float mean = st[c] * inv;
    float var = st[64 + c] * inv - mean * mean;
    float sc = gamma[c] * rsqrtf(var + 1e-5f);
    g_affine[layer * 128 + c]      = sc;
    g_affine[layer * 128 + 64 + c] = beta[c] - mean * sc;
}

// ---------------- pooling + head ----------------
__global__ void k_pool() {   // reads raw layer-4 output in g_bufA (fp32)
    int t = threadIdx.x;     // 256 threads
    float a0 = 0.f, a1 = 0.f;
    for (int n = blockIdx.x; n < N_NODES; n += gridDim.x) {
        float2 v = *(const float2*)(g_bufA + (size_t)n * FEAT + t * 2);
        a0 += v.x; a1 += v.y;
    }
    atomicAdd(&g_pool[t * 2], a0);
    atomicAdd(&g_pool[t * 2 + 1], a1);
}

__global__ void k_final(const float* __restrict__ wout,
                        const float* __restrict__ bout, float* __restrict__ o) {
    int m = threadIdx.x;
    if (m < 8) {
        const float* aff = g_affine + 4 * 128;
        float acc = bout[0];
        for (int c = 0; c < 64; c++)
            acc += wout[c] * (aff[c] * g_pool[c * 8 + m] * (1.0f / N_NODES) + aff[64 + c]);
        o[m] = 1.0f / (1.0f + expf(-acc));
    }
}

// ---------------- launch ----------------
extern "C" void kernel_launch(void* const* d_in, const int* in_sizes, int n_in,
                              void* d_out, int out_size) {
    const float* x     = (const float*)d_in[0];
    const void*  ei    = d_in[1];
    // d_in[2] = batch (unused, all zeros)
    const float* w10   = (const float*)d_in[3];
    const float* w1    = (const float*)d_in[4];
    const float* b1    = (const float*)d_in[5];
    const float* w2    = (const float*)d_in[6];
    const float* b2    = (const float*)d_in[7];
    const float* gamma = (const float*)d_in[8];
    const float* beta  = (const float*)d_in[9];
    const float* wout  = (const float*)d_in[10];
    const float* bout  = (const float*)d_in[11];
    float* out = (float*)d_out;

    k_init<<<(N_NODES + 255) / 256, 256>>>();
    k_detect<<<1, 32>>>(ei);
    k_prep<<<(9 * 4096 + 255) / 256, 256>>>(w1, w2);
    k_hist<<<(N_EDGES + 255) / 256, 256>>>(ei);
    k_scan<<<1, 1024>>>();
    k_fill<<<(N_EDGES + 255) / 256, 256>>>(ei);

    k_layer0<<<N_NODES / 8, 128>>>(x, w10, b1, b2);
    k_finalize<<<1, 64>>>(0, gamma, beta);
    for (int i = 1; i <= 4; i++) {
        k_gather<<<N_NODES / 4, 256>>>(i);
        k_mlp<<<N_NODES / 8, 128>>>(i, b1 + i * 64, b2 + i * 64);
        k_finalize<<<1, 64>>>(i, gamma + i * 64, beta + i * 64);
    }
    k_pool<<<256, 256>>>();
    k_final<<<1, 32>>>(wout, bout, out);
}

// round 6
// speedup vs baseline: 1.8605x; 1.1514x over previous
#include <cuda_runtime.h>
#include <cuda_fp16.h>
#include <cstdint>

// GIN: 5 layers, N=20000 nodes, E=320000 edges, HIDDEN=64, M=8.
//  - CSR build per launch (histogram + scan + fill).
//  - h lives ONLY as fp16 (g_hbuf); z is fp16 (g_z16). Everything L2-resident.
//  - k_gather: fp16 CSR gather (4-edge unrolled), fp32 accumulate, BN affine,
//    fp16 z out. k_mlp: z fp16 -> smem fp32 -> 2 GEMMs (fma.rn.f32x2) -> h fp16.
//  - BN folded to per-channel affine; finalize kernel per layer.

#define N_NODES 20000
#define N_EDGES 320000
#define HID 64
#define MDIM 8
#define FEAT (HID*MDIM)   // 512 elements per node

typedef unsigned long long ull;

// ---------------- device scratch ----------------
__device__ __half g_hbuf[N_NODES * FEAT];   // h fp16 (gather + pool source)
__device__ __half g_z16[N_NODES * FEAT];    // z fp16 scratch
__device__ int    g_rowptr[N_NODES + 1];
__device__ int    g_count[N_NODES];
__device__ int    g_fill[N_NODES];
__device__ int    g_srce[N_EDGES];
__device__ float  g_stats[5 * 128];         // per layer: sum[64], sumsq[64]
__device__ float  g_affine[5 * 128];        // per layer: scale[64], shift[64]
__device__ ull    g_Wt1p[4 * 4096];         // W1 layers 1..4, [c][o], (w,w) pairs
__device__ ull    g_Wt2p[5 * 4096];         // W2 layers 0..4, [c][o], (w,w) pairs
__device__ float  g_pool[FEAT];
__device__ int    g_is64;

// ---------------- f32x2 helpers ----------------
__device__ __forceinline__ ull pk2(float a, float b) {
    ull r; asm("mov.b64 %0, {%1, %2};" : "=l"(r) : "f"(a), "f"(b)); return r;
}
__device__ __forceinline__ float2 upk(ull v) {
    float2 r; asm("mov.b64 {%0, %1}, %2;" : "=f"(r.x), "=f"(r.y) : "l"(v)); return r;
}
__device__ __forceinline__ void fma2(ull& a, ull b, ull c) {
    asm("fma.rn.f32x2 %0, %1, %2, %0;" : "+l"(a) : "l"(b), "l"(c));
}

// ---------------- setup kernels ----------------
__global__ void k_init() {
    int i = blockIdx.x * blockDim.x + threadIdx.x;
    if (i < N_NODES) { g_count[i] = 0; g_fill[i] = 0; }
    if (i < 5 * 128) g_stats[i] = 0.f;
    if (i < FEAT)    g_pool[i] = 0.f;
}

__global__ void k_detect(const void* ei) {
    if (threadIdx.x == 0 && blockIdx.x == 0) {
        const ull* p = (const ull*)ei;
        int is64 = 1;
        for (int j = 0; j < 64; j++)
            if (p[j] >= (ull)N_NODES) is64 = 0;
        g_is64 = is64;
    }
}

__device__ __forceinline__ int edge_at(const void* ei, int idx) {
    return g_is64 ? (int)((const long long*)ei)[idx] : ((const int*)ei)[idx];
}

__global__ void k_hist(const void* ei) {
    int e = blockIdx.x * blockDim.x + threadIdx.x;
    if (e >= N_EDGES) return;
    atomicAdd(&g_count[edge_at(ei, N_EDGES + e)], 1);
}

__global__ void k_scan() {   // 1 block, 1024 threads, exclusive prefix over 20000
    __shared__ int s[1024];
    const int CH = 20;
    int t = threadIdx.x;
    int base = t * CH;
    int vals[CH];
    int local = 0;
#pragma unroll
    for (int j = 0; j < CH; j++) {
        int i = base + j;
        int v = (i < N_NODES) ? g_count[i] : 0;
        vals[j] = local; local += v;
    }
    s[t] = local;
    __syncthreads();
    for (int off = 1; off < 1024; off <<= 1) {
        int v = s[t];
        int add = (t >= off) ? s[t - off] : 0;
        __syncthreads();
        s[t] = v + add;
        __syncthreads();
    }
    int bb = (t == 0) ? 0 : s[t - 1];
#pragma unroll
    for (int j = 0; j < CH; j++) {
        int i = base + j;
        if (i < N_NODES) g_rowptr[i] = bb + vals[j];
    }
    if (t == 1023) g_rowptr[N_NODES] = s[1023];
}

__global__ void k_fill(const void* ei) {
    int e = blockIdx.x * blockDim.x + threadIdx.x;
    if (e >= N_EDGES) return;
    int srcv = edge_at(ei, e);
    int d    = edge_at(ei, N_EDGES + e);
    int pos  = g_rowptr[d] + atomicAdd(&g_fill[d], 1);
    g_srce[pos] = srcv;
}

// transpose + duplicate weights into (w,w) f32x2 pairs, layout [mat][c][o]
__global__ void k_prep(const float* __restrict__ w1, const float* __restrict__ w2) {
    int idx = blockIdx.x * blockDim.x + threadIdx.x;
    if (idx < 4 * 4096) {
        int mat = idx >> 12, r = idx & 4095, o = r >> 6, c = r & 63;
        float v = w1[idx];
        g_Wt1p[(mat << 12) + (c << 6) + o] = pk2(v, v);
    } else if (idx < 9 * 4096) {
        int j = idx - 4 * 4096;
        int mat = j >> 12, r = j & 4095, o = r >> 6, c = r & 63;
        float v = w2[j];
        g_Wt2p[(mat << 12) + (c << 6) + o] = pk2(v, v);
    }
}

// ---------------- GEMM core: out[o0..o0+3][m0..7] over K=64 ----------------
__device__ __forceinline__ void gemm64(const float* sIn, const ull* __restrict__ Wp,
                                       ull acc[16]) {
#pragma unroll
    for (int i = 0; i < 16; i++) acc[i] = 0ULL;
#pragma unroll 8
    for (int c = 0; c < 64; c++) {
        ulonglong2 wa = *(const ulonglong2*)(Wp + (c << 6));
        ulonglong2 wb = *(const ulonglong2*)(Wp + (c << 6) + 2);
        ulonglong2 za = *(const ulonglong2*)(sIn + (c << 3));
        ulonglong2 zb = *(const ulonglong2*)(sIn + (c << 3) + 4);
        ull w0 = wa.x, w1 = wa.y, w2 = wb.x, w3 = wb.y;
        ull z0 = za.x, z1 = za.y, z2 = zb.x, z3 = zb.y;
        fma2(acc[0],  w0, z0); fma2(acc[1],  w0, z1); fma2(acc[2],  w0, z2); fma2(acc[3],  w0, z3);
        fma2(acc[4],  w1, z0); fma2(acc[5],  w1, z1); fma2(acc[6],  w1, z2); fma2(acc[7],  w1, z3);
        fma2(acc[8],  w2, z0); fma2(acc[9],  w2, z1); fma2(acc[10], w2, z2); fma2(acc[11], w2, z3);
        fma2(acc[12], w3, z0); fma2(acc[13], w3, z1); fma2(acc[14], w3, z2); fma2(acc[15], w3, z3);
    }
}

// relu(acc + b1) -> shared
__device__ __forceinline__ void epi1(const ull acc[16], const float* sB1,
                                     float* sZg, int o0) {
#pragma unroll
    for (int r = 0; r < 4; r++) {
        float b = sB1[o0 + r];
        float2 p0 = upk(acc[r * 4 + 0]), p1 = upk(acc[r * 4 + 1]);
        float2 p2 = upk(acc[r * 4 + 2]), p3 = upk(acc[r * 4 + 3]);
        float4 v0, v1;
        v0.x = fmaxf(p0.x + b, 0.f); v0.y = fmaxf(p0.y + b, 0.f);
        v0.z = fmaxf(p1.x + b, 0.f); v0.w = fmaxf(p1.y + b, 0.f);
        v1.x = fmaxf(p2.x + b, 0.f); v1.y = fmaxf(p2.y + b, 0.f);
        v1.z = fmaxf(p3.x + b, 0.f); v1.w = fmaxf(p3.y + b, 0.f);
        *(float4*)(sZg + (o0 + r) * 8)     = v0;
        *(float4*)(sZg + (o0 + r) * 8 + 4) = v1;
    }
}

// relu(acc + b2) -> fp16 h row + BN stat accumulation
__device__ __forceinline__ void epi2(const ull acc[16], const float* sB2,
                                     __half* outh, int o0, float* sStats) {
#pragma unroll
    for (int r = 0; r < 4; r++) {
        int o = o0 + r;
        float b = sB2[o];
        float2 p0 = upk(acc[r * 4 + 0]), p1 = upk(acc[r * 4 + 1]);
        float2 p2 = upk(acc[r * 4 + 2]), p3 = upk(acc[r * 4 + 3]);
        float f0 = fmaxf(p0.x + b, 0.f), f1 = fmaxf(p0.y + b, 0.f);
        float f2 = fmaxf(p1.x + b, 0.f), f3 = fmaxf(p1.y + b, 0.f);
        float f4 = fmaxf(p2.x + b, 0.f), f5 = fmaxf(p2.y + b, 0.f);
        float f6 = fmaxf(p3.x + b, 0.f), f7 = fmaxf(p3.y + b, 0.f);
        __half2 h0 = __floats2half2_rn(f0, f1);
        __half2 h1 = __floats2half2_rn(f2, f3);
        __half2 h2 = __floats2half2_rn(f4, f5);
        __half2 h3 = __floats2half2_rn(f6, f7);
        uint4 hv;
        hv.x = *(unsigned*)&h0; hv.y = *(unsigned*)&h1;
        hv.z = *(unsigned*)&h2; hv.w = *(unsigned*)&h3;
        *(uint4*)(outh + o * 8) = hv;
        float s = f0 + f1 + f2 + f3 + f4 + f5 + f6 + f7;
        float q = f0*f0 + f1*f1 + f2*f2 + f3*f3 + f4*f4 + f5*f5 + f6*f6 + f7*f7;
        s += __shfl_xor_sync(0xffffffffu, s, 16);
        q += __shfl_xor_sync(0xffffffffu, q, 16);
        if ((threadIdx.x & 16) == 0) {
            atomicAdd(&sStats[o], s);
            atomicAdd(&sStats[64 + o], q);
        }
    }
}

// ---------------- layer 0 (IN_DIM=1) ----------------
__global__ void __launch_bounds__(128) k_layer0(
    const float* __restrict__ x, const float* __restrict__ w10,
    const float* __restrict__ b1, const float* __restrict__ b2) {
    __shared__ float sZ[8 * FEAT];
    __shared__ float sZ0[64];
    __shared__ float sStats[128];
    __shared__ float sB2[64];
    int t = threadIdx.x;
    sStats[t] = 0.f;
    if (t < 64) sB2[t] = b2[t];
    int g = t >> 4, l = t & 15;
    int n = (blockIdx.x << 3) + g;
    if (l < 8) {
        float a = x[n * 8 + l];
        int rs = g_rowptr[n], re = g_rowptr[n + 1];
        for (int e = rs; e < re; e++) a += x[g_srce[e] * 8 + l];
        sZ0[g * 8 + l] = a;
    }
    __syncthreads();
    int o0 = l << 2;
    float zz[8];
#pragma unroll
    for (int m = 0; m < 8; m++) zz[m] = sZ0[g * 8 + m];
#pragma unroll
    for (int r = 0; r < 4; r++) {
        int o = o0 + r;
        float w = w10[o], b = b1[o];
        float4 v0, v1;
        v0.x = fmaxf(w * zz[0] + b, 0.f); v0.y = fmaxf(w * zz[1] + b, 0.f);
        v0.z = fmaxf(w * zz[2] + b, 0.f); v0.w = fmaxf(w * zz[3] + b, 0.f);
        v1.x = fmaxf(w * zz[4] + b, 0.f); v1.y = fmaxf(w * zz[5] + b, 0.f);
        v1.z = fmaxf(w * zz[6] + b, 0.f); v1.w = fmaxf(w * zz[7] + b, 0.f);
        *(float4*)(sZ + (g << 9) + o * 8)     = v0;
        *(float4*)(sZ + (g << 9) + o * 8 + 4) = v1;
    }
    __syncthreads();
    ull acc[16];
    gemm64(sZ + (g << 9), g_Wt2p + o0, acc);
    epi2(acc, sB2, g_hbuf + (size_t)n * FEAT, o0, sStats);
    __syncthreads();
    atomicAdd(&g_stats[t], sStats[t]);
}

// ---------------- gather (layers 1..4): fp16 CSR gather + BN affine -> z fp16 ----
__device__ __forceinline__ void acc8(float a[8], uint4 v) {
    float2 p;
    p = __half22float2(*(const __half2*)&v.x); a[0] += p.x; a[1] += p.y;
    p = __half22float2(*(const __half2*)&v.y); a[2] += p.x; a[3] += p.y;
    p = __half22float2(*(const __half2*)&v.z); a[4] += p.x; a[5] += p.y;
    p = __half22float2(*(const __half2*)&v.w); a[6] += p.x; a[7] += p.y;
}

__global__ void __launch_bounds__(256) k_gather(int layer) {
    const uint4* __restrict__ in = (const uint4*)g_hbuf;  // 64 uint4 per node row
    int t = threadIdx.x;
    int grp = t >> 6;          // node within block: 0..3
    int l = t & 63;            // channel
    int n = (blockIdx.x << 2) + grp;
    int rs = g_rowptr[n], re = g_rowptr[n + 1];
    float sc = g_affine[(layer - 1) * 128 + l];
    float sh = g_affine[(layer - 1) * 128 + 64 + l];
    float a[8] = {0,0,0,0,0,0,0,0}, b[8] = {0,0,0,0,0,0,0,0};
    acc8(a, in[(size_t)n * 64 + l]);   // self
    int e = rs;
    for (; e + 4 <= re; e += 4) {
        int s0 = g_srce[e], s1 = g_srce[e + 1], s2 = g_srce[e + 2], s3 = g_srce[e + 3];
        uint4 v0 = in[(size_t)s0 * 64 + l];
        uint4 v1 = in[(size_t)s1 * 64 + l];
        uint4 v2 = in[(size_t)s2 * 64 + l];
        uint4 v3 = in[(size_t)s3 * 64 + l];
        acc8(a, v0); acc8(b, v1); acc8(a, v2); acc8(b, v3);
    }
    for (; e < re; e++) acc8(a, in[(size_t)g_srce[e] * 64 + l]);
    float shd = sh * (float)(re - rs + 1);
    float f0 = sc * (a[0] + b[0]) + shd, f1 = sc * (a[1] + b[1]) + shd;
    float f2 = sc * (a[2] + b[2]) + shd, f3 = sc * (a[3] + b[3]) + shd;
    float f4 = sc * (a[4] + b[4]) + shd, f5 = sc * (a[5] + b[5]) + shd;
    float f6 = sc * (a[6] + b[6]) + shd, f7 = sc * (a[7] + b[7]) + shd;
    __half2 h0 = __floats2half2_rn(f0, f1);
    __half2 h1 = __floats2half2_rn(f2, f3);
    __half2 h2 = __floats2half2_rn(f4, f5);
    __half2 h3 = __floats2half2_rn(f6, f7);
    uint4 hv;
    hv.x = *(unsigned*)&h0; hv.y = *(unsigned*)&h1;
    hv.z = *(unsigned*)&h2; hv.w = *(unsigned*)&h3;
    *(uint4*)(g_z16 + (size_t)n * FEAT + (l << 3)) = hv;
}

// ---------------- MLP (layers 1..4): z fp16 -> 2 GEMMs -> h fp16 (+BN stats) ----
__global__ void __launch_bounds__(128) k_mlp(
    int layer, const float* __restrict__ b1, const float* __restrict__ b2) {
    __shared__ float sZ[8 * FEAT];    // 16 KB, reused z -> y
    __shared__ float sStats[128];
    __shared__ float sB1[64], sB2[64];
    int t = threadIdx.x;
    sStats[t] = 0.f;
    if (t < 64) { sB1[t] = b1[t]; sB2[t] = b2[t]; }
    // cooperative load: 8 node rows fp16 (512 uint4), convert to fp32 smem
    const uint4* src = (const uint4*)(g_z16 + (size_t)(blockIdx.x << 3) * FEAT);
#pragma unroll
    for (int j = 0; j < 4; j++) {
        int i = t + 128 * j;          // uint4 index in block tile
        uint4 v = src[i];
        float* d = sZ + i * 8;
        float2 p;
        p = __half22float2(*(const __half2*)&v.x); d[0] = p.x; d[1] = p.y;
        p = __half22float2(*(const __half2*)&v.y); d[2] = p.x; d[3] = p.y;
        p = __half22float2(*(const __half2*)&v.z); d[4] = p.x; d[5] = p.y;
        p = __half22float2(*(const __half2*)&v.w); d[6] = p.x; d[7] = p.y;
    }
    __syncthreads();
    int g = t >> 4, l = t & 15, o0 = l << 2;
    int n = (blockIdx.x << 3) + g;
    ull acc[16];
    gemm64(sZ + (g << 9), g_Wt1p + ((layer - 1) << 12) + o0, acc);
    __syncthreads();
    epi1(acc, sB1, sZ + (g << 9), o0);
    __syncthreads();
    gemm64(sZ + (g << 9), g_Wt2p + (layer << 12) + o0, acc);
    epi2(acc, sB2, g_hbuf + (size_t)n * FEAT, o0, sStats);
    __syncthreads();
    atomicAdd(&g_stats[layer * 128 + t], sStats[t]);
}

// ---------------- BN finalize: stats -> (scale, shift) ----------------
__global__ void k_finalize(int layer, const float* __restrict__ gamma,
                           const float* __restrict__ beta) {
    int c = threadIdx.x;  // 64 threads
    const float* st = g_stats + layer * 128;
    float inv = 1.0f / 160000.0f;
    float mean = st[c] * inv;
    float var = st[64 + c] * inv - mean * mean;
    float sc = gamma[c] * rsqrtf(var + 1e-5f);
    g_affine[layer * 128 + c]      = sc;
    g_affine[layer * 128 + 64 + c] = beta[c] - mean * sc;
}

// ---------------- pooling + head ----------------
__global__ void k_pool() {   // reads raw layer-4 fp16 output in g_hbuf
    int t = threadIdx.x;     // 256 threads; each handles 2 consecutive elements
    float a0 = 0.f, a1 = 0.f;
    for (int n = blockIdx.x; n < N_NODES; n += gridDim.x) {
        __half2 v = *(const __half2*)(g_hbuf + (size_t)n * FEAT + t * 2);
        float2 p = __half22float2(v);
        a0 += p.x; a1 += p.y;
    }
    atomicAdd(&g_pool[t * 2], a0);
    atomicAdd(&g_pool[t * 2 + 1], a1);
}

__global__ void k_final(const float* __restrict__ wout,
                        const float* __restrict__ bout, float* __restrict__ o) {
    int m = threadIdx.x;
    if (m < 8) {
        const float* aff = g_affine + 4 * 128;
        float acc = bout[0];
        for (int c = 0; c < 64; c++)
            acc += wout[c] * (aff[c] * g_pool[c * 8 + m] * (1.0f / N_NODES) + aff[64 + c]);
        o[m] = 1.0f / (1.0f + expf(-acc));
    }
}

// ---------------- launch ----------------
extern "C" void kernel_launch(void* const* d_in, const int* in_sizes, int n_in,
                              void* d_out, int out_size) {
    const float* x     = (const float*)d_in[0];
    const void*  ei    = d_in[1];
    // d_in[2] = batch (unused, all zeros)
    const float* w10   = (const float*)d_in[3];
    const float* w1    = (const float*)d_in[4];
    const float* b1    = (const float*)d_in[5];
    const float* w2    = (const float*)d_in[6];
    const float* b2    = (const float*)d_in[7];
    const float* gamma = (const float*)d_in[8];
    const float* beta  = (const float*)d_in[9];
    const float* wout  = (const float*)d_in[10];
    const float* bout  = (const float*)d_in[11];
    float* out = (float*)d_out;

    k_init<<<(N_NODES + 255) / 256, 256>>>();
    k_detect<<<1, 32>>>(ei);
    k_prep<<<(9 * 4096 + 255) / 256, 256>>>(w1, w2);
    k_hist<<<(N_EDGES + 255) / 256, 256>>>(ei);
    k_scan<<<1, 1024>>>();
    k_fill<<<(N_EDGES + 255) / 256, 256>>>(ei);

    k_layer0<<<N_NODES / 8, 128>>>(x, w10, b1, b2);
    k_finalize<<<1, 64>>>(0, gamma, beta);
    for (int i = 1; i <= 4; i++) {
        k_gather<<<N_NODES / 4, 256>>>(i);
        k_mlp<<<N_NODES / 8, 128>>>(i, b1 + i * 64, b2 + i * 64);
        k_finalize<<<1, 64>>>(i, gamma + i * 64, beta + i * 64);
    }
    k_pool<<<256, 256>>>();
    k_final<<<1, 32>>>(wout, bout, out);
}

// round 8
// speedup vs baseline: 2.1669x; 1.1647x over previous
#include <cuda_runtime.h>
#include <cuda_fp16.h>
#include <cstdint>

// GIN: 5 layers, N=20000 nodes, E=320000 edges, HIDDEN=64, M=8.
//  - CSR build per launch (histogram + scan + fill).
//  - h/z fp16, L2-resident. k_gather: fp16 CSR gather + BN affine -> z fp16.
//  - k_mlp: tensor-core HMMA (m16n8k16) per-node GEMM pair W*Z keeping [c][m]
//    layout invariant; relu + bias + BN-stat epilogue. Weights fp16 in smem.
//  - BN folded to per-channel affine; finalize kernel per layer.

#define N_NODES 20000
#define N_EDGES 320000
#define HID 64
#define MDIM 8
#define FEAT (HID*MDIM)   // 512 elements per node

typedef unsigned long long ull;

// ---------------- device scratch ----------------
__device__ __half g_hbuf[N_NODES * FEAT];   // h fp16 (gather + pool source)
__device__ __half g_z16[N_NODES * FEAT];    // z fp16 scratch
__device__ int    g_rowptr[N_NODES + 1];
__device__ int    g_count[N_NODES];
__device__ int    g_fill[N_NODES];
__device__ int    g_srce[N_EDGES];
__device__ float  g_stats[5 * 128];         // per layer: sum[64], sumsq[64]
__device__ float  g_affine[5 * 128];        // per layer: scale[64], shift[64]
__device__ ull    g_Wt2p[4096];             // W2 layer 0 (layer0 FFMA2 path), [c][o] pairs
__device__ __half g_W1h[4 * 4096];          // W1 layers 1..4, [o][c] fp16
__device__ __half g_W2h[5 * 4096];          // W2 layers 0..4, [o][c] fp16
__device__ float  g_pool[FEAT];
__device__ int    g_is64;

// ---------------- helpers ----------------
__device__ __forceinline__ ull pk2(float a, float b) {
    ull r; asm("mov.b64 %0, {%1, %2};" : "=l"(r) : "f"(a), "f"(b)); return r;
}
__device__ __forceinline__ float2 upk(ull v) {
    float2 r; asm("mov.b64 {%0, %1}, %2;" : "=f"(r.x), "=f"(r.y) : "l"(v)); return r;
}
__device__ __forceinline__ void fma2(ull& a, ull b, ull c) {
    asm("fma.rn.f32x2 %0, %1, %2, %0;" : "+l"(a) : "l"(b), "l"(c));
}
__device__ __forceinline__ uint32_t smem_u32(const void* p) {
    return (uint32_t)__cvta_generic_to_shared(p);
}
__device__ __forceinline__ void ldmA(unsigned a[4], uint32_t addr) {
    asm volatile("ldmatrix.sync.aligned.m8n8.x4.shared.b16 {%0,%1,%2,%3}, [%4];"
        : "=r"(a[0]), "=r"(a[1]), "=r"(a[2]), "=r"(a[3]) : "r"(addr));
}
__device__ __forceinline__ void ldmBt(unsigned b[2], uint32_t addr) {
    asm volatile("ldmatrix.sync.aligned.m8n8.x2.trans.shared.b16 {%0,%1}, [%2];"
        : "=r"(b[0]), "=r"(b[1]) : "r"(addr));
}
__device__ __forceinline__ void mma16816(float d[4], const unsigned a[4], const unsigned b[2]) {
    asm volatile("mma.sync.aligned.m16n8k16.row.col.f32.f16.f16.f32 "
        "{%0,%1,%2,%3}, {%4,%5,%6,%7}, {%8,%9}, {%0,%1,%2,%3};"
        : "+f"(d[0]), "+f"(d[1]), "+f"(d[2]), "+f"(d[3])
        : "r"(a[0]), "r"(a[1]), "r"(a[2]), "r"(a[3]), "r"(b[0]), "r"(b[1]));
}

// ---------------- setup kernels ----------------
__global__ void k_init() {
    int i = blockIdx.x * blockDim.x + threadIdx.x;
    if (i < N_NODES) { g_count[i] = 0; g_fill[i] = 0; }
    if (i < 5 * 128) g_stats[i] = 0.f;
    if (i < FEAT)    g_pool[i] = 0.f;
}

__global__ void k_detect(const void* ei) {
    if (threadIdx.x == 0 && blockIdx.x == 0) {
        const ull* p = (const ull*)ei;
        int is64 = 1;
        for (int j = 0; j < 64; j++)
            if (p[j] >= (ull)N_NODES) is64 = 0;
        g_is64 = is64;
    }
}

__device__ __forceinline__ int edge_at(const void* ei, int idx) {
    return g_is64 ? (int)((const long long*)ei)[idx] : ((const int*)ei)[idx];
}

__global__ void k_hist(const void* ei) {
    int e = blockIdx.x * blockDim.x + threadIdx.x;
    if (e >= N_EDGES) return;
    atomicAdd(&g_count[edge_at(ei, N_EDGES + e)], 1);
}

__global__ void k_scan() {   // 1 block, 1024 threads, exclusive prefix over 20000
    __shared__ int s[1024];
    const int CH = 20;
    int t = threadIdx.x;
    int base = t * CH;
    int vals[CH];
    int local = 0;
#pragma unroll
    for (int j = 0; j < CH; j++) {
        int i = base + j;
        int v = (i < N_NODES) ? g_count[i] : 0;
        vals[j] = local; local += v;
    }
    s[t] = local;
    __syncthreads();
    for (int off = 1; off < 1024; off <<= 1) {
        int v = s[t];
        int add = (t >= off) ? s[t - off] : 0;
        __syncthreads();
        s[t] = v + add;
        __syncthreads();
    }
    int bb = (t == 0) ? 0 : s[t - 1];
#pragma unroll
    for (int j = 0; j < CH; j++) {
        int i = base + j;
        if (i < N_NODES) g_rowptr[i] = bb + vals[j];
    }
    if (t == 1023) g_rowptr[N_NODES] = s[1023];
}

__global__ void k_fill(const void* ei) {
    int e = blockIdx.x * blockDim.x + threadIdx.x;
    if (e >= N_EDGES) return;
    int srcv = edge_at(ei, e);
    int d    = edge_at(ei, N_EDGES + e);
    int pos  = g_rowptr[d] + atomicAdd(&g_fill[d], 1);
    g_srce[pos] = srcv;
}

// weight prep: fp16 copies of W1 (layers 1..4) and W2 (0..4), [o][c] layout
// (same as source), plus fp32 (w,w) pairs [c][o] for layer0's FFMA2 path.
__global__ void k_prep(const float* __restrict__ w1, const float* __restrict__ w2) {
    int idx = blockIdx.x * blockDim.x + threadIdx.x;
    if (idx < 4 * 4096) {
        g_W1h[idx] = __float2half(w1[idx]);
    } else if (idx < 9 * 4096) {
        int j = idx - 4 * 4096;
        float v = w2[j];
        g_W2h[j] = __float2half(v);
        if (j < 4096) {   // layer0 W2 fp32 pairs, transposed [c][o]
            int o = j >> 6, c = j & 63;
            g_Wt2p[(c << 6) + o] = pk2(v, v);
        }
    }
}

// ---------------- layer0 FFMA2 GEMM core (once per launch) ----------------
__device__ __forceinline__ void gemm64(const float* sIn, const ull* __restrict__ Wp,
                                       ull acc[16]) {
#pragma unroll
    for (int i = 0; i < 16; i++) acc[i] = 0ULL;
#pragma unroll 8
    for (int c = 0; c < 64; c++) {
        ulonglong2 wa = *(const ulonglong2*)(Wp + (c << 6));
        ulonglong2 wb = *(const ulonglong2*)(Wp + (c << 6) + 2);
        ulonglong2 za = *(const ulonglong2*)(sIn + (c << 3));
        ulonglong2 zb = *(const ulonglong2*)(sIn + (c << 3) + 4);
        ull w0 = wa.x, w1 = wa.y, w2 = wb.x, w3 = wb.y;
        ull z0 = za.x, z1 = za.y, z2 = zb.x, z3 = zb.y;
        fma2(acc[0],  w0, z0); fma2(acc[1],  w0, z1); fma2(acc[2],  w0, z2); fma2(acc[3],  w0, z3);
        fma2(acc[4],  w1, z0); fma2(acc[5],  w1, z1); fma2(acc[6],  w1, z2); fma2(acc[7],  w1, z3);
        fma2(acc[8],  w2, z0); fma2(acc[9],  w2, z1); fma2(acc[10], w2, z2); fma2(acc[11], w2, z3);
        fma2(acc[12], w3, z0); fma2(acc[13], w3, z1); fma2(acc[14], w3, z2); fma2(acc[15], w3, z3);
    }
}

// relu(acc + b2) -> fp16 h row + BN stat accumulation (layer0 epilogue)
__device__ __forceinline__ void epi2(const ull acc[16], const float* sB2,
                                     __half* outh, int o0, float* sStats) {
#pragma unroll
    for (int r = 0; r < 4; r++) {
        int o = o0 + r;
        float b = sB2[o];
        float2 p0 = upk(acc[r * 4 + 0]), p1 = upk(acc[r * 4 + 1]);
        float2 p2 = upk(acc[r * 4 + 2]), p3 = upk(acc[r * 4 + 3]);
        float f0 = fmaxf(p0.x + b, 0.f), f1 = fmaxf(p0.y + b, 0.f);
        float f2 = fmaxf(p1.x + b, 0.f), f3 = fmaxf(p1.y + b, 0.f);
        float f4 = fmaxf(p2.x + b, 0.f), f5 = fmaxf(p2.y + b, 0.f);
        float f6 = fmaxf(p3.x + b, 0.f), f7 = fmaxf(p3.y + b, 0.f);
        __half2 h0 = __floats2half2_rn(f0, f1);
        __half2 h1 = __floats2half2_rn(f2, f3);
        __half2 h2 = __floats2half2_rn(f4, f5);
        __half2 h3 = __floats2half2_rn(f6, f7);
        uint4 hv;
        hv.x = *(unsigned*)&h0; hv.y = *(unsigned*)&h1;
        hv.z = *(unsigned*)&h2; hv.w = *(unsigned*)&h3;
        *(uint4*)(outh + o * 8) = hv;
        float s = f0 + f1 + f2 + f3 + f4 + f5 + f6 + f7;
        float q = f0*f0 + f1*f1 + f2*f2 + f3*f3 + f4*f4 + f5*f5 + f6*f6 + f7*f7;
        s += __shfl_xor_sync(0xffffffffu, s, 16);
        q += __shfl_xor_sync(0xffffffffu, q, 16);
        if ((threadIdx.x & 16) == 0) {
            atomicAdd(&sStats[o], s);
            atomicAdd(&sStats[64 + o], q);
        }
    }
}

// ---------------- layer 0 (IN_DIM=1) ----------------
__global__ void __launch_bounds__(128) k_layer0(
    const float* __restrict__ x, const float* __restrict__ w10,
    const float* __restrict__ b1, const float* __restrict__ b2) {
    __shared__ float sZ[8 * FEAT];
    __shared__ float sZ0[64];
    __shared__ float sStats[128];
    __shared__ float sB2[64];
    int t = threadIdx.x;
    sStats[t] = 0.f;
    if (t < 64) sB2[t] = b2[t];
    int g = t >> 4, l = t & 15;
    int n = (blockIdx.x << 3) + g;
    if (l < 8) {
        float a = x[n * 8 + l];
        int rs = g_rowptr[n], re = g_rowptr[n + 1];
        for (int e = rs; e < re; e++) a += x[g_srce[e] * 8 + l];
        sZ0[g * 8 + l] = a;
    }
    __syncthreads();
    int o0 = l << 2;
    float zz[8];
#pragma unroll
    for (int m = 0; m < 8; m++) zz[m] = sZ0[g * 8 + m];
#pragma unroll
    for (int r = 0; r < 4; r++) {
        int o = o0 + r;
        float w = w10[o], b = b1[o];
        float4 v0, v1;
        v0.x = fmaxf(w * zz[0] + b, 0.f); v0.y = fmaxf(w * zz[1] + b, 0.f);
        v0.z = fmaxf(w * zz[2] + b, 0.f); v0.w = fmaxf(w * zz[3] + b, 0.f);
        v1.x = fmaxf(w * zz[4] + b, 0.f); v1.y = fmaxf(w * zz[5] + b, 0.f);
        v1.z = fmaxf(w * zz[6] + b, 0.f); v1.w = fmaxf(w * zz[7] + b, 0.f);
        *(float4*)(sZ + (g << 9) + o * 8)     = v0;
        *(float4*)(sZ + (g << 9) + o * 8 + 4) = v1;
    }
    __syncthreads();
    ull acc[16];
    gemm64(sZ + (g << 9), g_Wt2p + o0, acc);
    epi2(acc, sB2, g_hbuf + (size_t)n * FEAT, o0, sStats);
    __syncthreads();
    atomicAdd(&g_stats[t], sStats[t]);
}

// ---------------- gather (layers 1..4): fp16 CSR gather + BN affine -> z fp16 ----
__device__ __forceinline__ void acc8(float a[8], uint4 v) {
    float2 p;
    p = __half22float2(*(const __half2*)&v.x); a[0] += p.x; a[1] += p.y;
    p = __half22float2(*(const __half2*)&v.y); a[2] += p.x; a[3] += p.y;
    p = __half22float2(*(const __half2*)&v.z); a[4] += p.x; a[5] += p.y;
    p = __half22float2(*(const __half2*)&v.w); a[6] += p.x; a[7] += p.y;
}

__global__ void __launch_bounds__(256) k_gather(int layer) {
    const uint4* __restrict__ in = (const uint4*)g_hbuf;  // 64 uint4 per node row
    int t = threadIdx.x;
    int grp = t >> 6;          // node within block: 0..3
    int l = t & 63;            // channel
    int n = (blockIdx.x << 2) + grp;
    int rs = g_rowptr[n], re = g_rowptr[n + 1];
    float sc = g_affine[(layer - 1) * 128 + l];
    float sh = g_affine[(layer - 1) * 128 + 64 + l];
    float a[8] = {0,0,0,0,0,0,0,0}, b[8] = {0,0,0,0,0,0,0,0};
    acc8(a, in[(size_t)n * 64 + l]);   // self
    int e = rs;
    for (; e + 4 <= re; e += 4) {
        int s0 = g_srce[e], s1 = g_srce[e + 1], s2 = g_srce[e + 2], s3 = g_srce[e + 3];
        uint4 v0 = in[(size_t)s0 * 64 + l];
        uint4 v1 = in[(size_t)s1 * 64 + l];
        uint4 v2 = in[(size_t)s2 * 64 + l];
        uint4 v3 = in[(size_t)s3 * 64 + l];
        acc8(a, v0); acc8(b, v1); acc8(a, v2); acc8(b, v3);
    }
    for (; e < re; e++) acc8(a, in[(size_t)g_srce[e] * 64 + l]);
    float shd = sh * (float)(re - rs + 1);
    float f0 = sc * (a[0] + b[0]) + shd, f1 = sc * (a[1] + b[1]) + shd;
    float f2 = sc * (a[2] + b[2]) + shd, f3 = sc * (a[3] + b[3]) + shd;
    float f4 = sc * (a[4] + b[4]) + shd, f5 = sc * (a[5] + b[5]) + shd;
    float f6 = sc * (a[6] + b[6]) + shd, f7 = sc * (a[7] + b[7]) + shd;
    __half2 h0 = __floats2half2_rn(f0, f1);
    __half2 h1 = __floats2half2_rn(f2, f3);
    __half2 h2 = __floats2half2_rn(f4, f5);
    __half2 h3 = __floats2half2_rn(f6, f7);
    uint4 hv;
    hv.x = *(unsigned*)&h0; hv.y = *(unsigned*)&h1;
    hv.z = *(unsigned*)&h2; hv.w = *(unsigned*)&h3;
    *(uint4*)(g_z16 + (size_t)n * FEAT + (l << 3)) = hv;
}

// ---------------- MLP (layers 1..4): tensor-core GEMM pair ----------------
// 256 threads = 8 warps, 1 node per warp, 8 nodes per block.
// Y = W x Znode : A = W[o][c] (row-major), B = z node tile [c][m] -> D[o][m]
// keeps the [c][m] layout invariant between the two GEMMs.
__global__ void __launch_bounds__(256) k_mlp(
    int layer, const float* __restrict__ b1, const float* __restrict__ b2) {
    __shared__ __half sW1[4096];
    __shared__ __half sW2[4096];
    __shared__ __half sZ[8 * FEAT];   // 8 node tiles [c64][m8], reused z -> y
    __shared__ float sStats[128];
    __shared__ float sB1[64], sB2[64];
    int t = threadIdx.x;
    int w = t >> 5, lane = t & 31;
    if (t < 128) sStats[t] = 0.f;
    if (t < 64) { sB1[t] = b1[t]; sB2[t] = b2[t]; }
    // stage weights (512 uint4 each) + z tile (512 uint4)
    const uint4* w1src = (const uint4*)(g_W1h + (size_t)(layer - 1) * 4096);
    const uint4* w2src = (const uint4*)(g_W2h + (size_t)layer * 4096);
    const uint4* zsrc  = (const uint4*)(g_z16 + (size_t)(blockIdx.x << 3) * FEAT);
    ((uint4*)sW1)[t] = w1src[t];  ((uint4*)sW1)[t + 256] = w1src[t + 256];
    ((uint4*)sW2)[t] = w2src[t];  ((uint4*)sW2)[t + 256] = w2src[t + 256];
    ((uint4*)sZ)[t]  = zsrc[t];   ((uint4*)sZ)[t + 256]  = zsrc[t + 256];
    __syncthreads();

    int n = (blockIdx.x << 3) + w;
    uint32_t zbase = smem_u32(sZ + w * FEAT);
    int r = lane >> 2, q = lane & 3;

    // ---- GEMM1 ----
    unsigned bf[4][2];
#pragma unroll
    for (int k = 0; k < 4; k++)
        ldmBt(bf[k], zbase + ((k * 16 + (lane & 15)) * 8) * 2);
    uint32_t w1base = smem_u32(sW1);
    float acc[4][4];
#pragma unroll
    for (int ot = 0; ot < 4; ot++) {
#pragma unroll
        for (int i = 0; i < 4; i++) acc[ot][i] = 0.f;
#pragma unroll
        for (int k = 0; k < 4; k++) {
            unsigned af[4];
            ldmA(af, w1base + (((ot * 16 + (lane & 15)) * 64) + k * 16 + ((lane >> 4) << 3)) * 2);
            mma16816(acc[ot], af, bf[k]);
        }
    }
    // epilogue 1: y = relu(acc + b1) -> overwrite own z tile (warp-private)
#pragma unroll
    for (int ot = 0; ot < 4; ot++) {
        int oa = ot * 16 + r, ob = oa + 8;
        float ba = sB1[oa], bb = sB1[ob];
        __half2 ya = __floats2half2_rn(fmaxf(acc[ot][0] + ba, 0.f), fmaxf(acc[ot][1] + ba, 0.f));
        __half2 yb = __floats2half2_rn(fmaxf(acc[ot][2] + bb, 0.f), fmaxf(acc[ot][3] + bb, 0.f));
        *(__half2*)(sZ + w * FEAT + oa * 8 + 2 * q) = ya;
        *(__half2*)(sZ + w * FEAT + ob * 8 + 2 * q) = yb;
    }
    __syncwarp();

    // ---- GEMM2 ----
#pragma unroll
    for (int k = 0; k < 4; k++)
        ldmBt(bf[k], zbase + ((k * 16 + (lane & 15)) * 8) * 2);
    uint32_t w2base = smem_u32(sW2);
#pragma unroll
    for (int ot = 0; ot < 4; ot++) {
#pragma unroll
        for (int i = 0; i < 4; i++) acc[ot][i] = 0.f;
#pragma unroll
        for (int k = 0; k < 4; k++) {
            unsigned af[4];
            ldmA(af, w2base + (((ot * 16 + (lane & 15)) * 64) + k * 16 + ((lane >> 4) << 3)) * 2);
            mma16816(acc[ot], af, bf[k]);
        }
    }
    // epilogue 2: h = relu(acc + b2) -> global fp16 + stats
    __half* hrow = g_hbuf + (size_t)n * FEAT;
#pragma unroll
    for (int ot = 0; ot < 4; ot++) {
        int oa = ot * 16 + r, ob = oa + 8;
        float ba = sB2[oa], bb = sB2[ob];
        float f0 = fmaxf(acc[ot][0] + ba, 0.f), f1 = fmaxf(acc[ot][1] + ba, 0.f);
        float f2 = fmaxf(acc[ot][2] + bb, 0.f), f3 = fmaxf(acc[ot][3] + bb, 0.f);
        *(__half2*)(hrow + oa * 8 + 2 * q) = __floats2half2_rn(f0, f1);
        *(__half2*)(hrow + ob * 8 + 2 * q) = __floats2half2_rn(f2, f3);
        float sa = f0 + f1, qa = f0 * f0 + f1 * f1;
        float sb = f2 + f3, qb = f2 * f2 + f3 * f3;
        sa += __shfl_xor_sync(0xffffffffu, sa, 1); sa += __shfl_xor_sync(0xffffffffu, sa, 2);
        qa += __shfl_xor_sync(0xffffffffu, qa, 1); qa += __shfl_xor_sync(0xffffffffu, qa, 2);
        sb += __shfl_xor_sync(0xffffffffu, sb, 1); sb += __shfl_xor_sync(0xffffffffu, sb, 2);
        qb += __shfl_xor_sync(0xffffffffu, qb, 1); qb += __shfl_xor_sync(0xffffffffu, qb, 2);
        if (q == 0) {
            atomicAdd(&sStats[oa], sa);
            atomicAdd(&sStats[64 + oa], qa);
            atomicAdd(&sStats[ob], sb);
            atomicAdd(&sStats[64 + ob], qb);
        }
    }
    __syncthreads();
    if (t < 128) atomicAdd(&g_stats[layer * 128 + t], sStats[t]);
}

// ---------------- BN finalize: stats -> (scale, shift) ----------------
__global__ void k_finalize(int layer, const float* __restrict__ gamma,
                           const float* __restrict__ beta) {
    int c = threadIdx.x;  // 64 threads
    const float* st = g_stats + layer * 128;
    float inv = 1.0f / 160000.0f;
    float mean = st[c] * inv;
    float var = st[64 + c] * inv - mean * mean;
    float sc = gamma[c] * rsqrtf(var + 1e-5f);
    g_affine[layer * 128 + c]      = sc;
    g_affine[layer * 128 + 64 + c] = beta[c] - mean * sc;
}

// ---------------- pooling + head ----------------
__global__ void k_pool() {   // reads raw layer-4 fp16 output in g_hbuf
    int t = threadIdx.x;     // 256 threads; each handles 2 consecutive elements
    float a0 = 0.f, a1 = 0.f;
    for (int n = blockIdx.x; n < N_NODES; n += gridDim.x) {
        __half2 v = *(const __half2*)(g_hbuf + (size_t)n * FEAT + t * 2);
        float2 p = __half22float2(v);
        a0 += p.x; a1 += p.y;
    }
    atomicAdd(&g_pool[t * 2], a0);
    atomicAdd(&g_pool[t * 2 + 1], a1);
}

__global__ void k_final(const float* __restrict__ wout,
                        const float* __restrict__ bout, float* __restrict__ o) {
    int m = threadIdx.x;
    if (m < 8) {
        const float* aff = g_affine + 4 * 128;
        float acc = bout[0];
        for (int c = 0; c < 64; c++)
            acc += wout[c] * (aff[c] * g_pool[c * 8 + m] * (1.0f / N_NODES) + aff[64 + c]);
        o[m] = 1.0f / (1.0f + expf(-acc));
    }
}

// ---------------- launch ----------------
extern "C" void kernel_launch(void* const* d_in, const int* in_sizes, int n_in,
                              void* d_out, int out_size) {
    const float* x     = (const float*)d_in[0];
    const void*  ei    = d_in[1];
    // d_in[2] = batch (unused, all zeros)
    const float* w10   = (const float*)d_in[3];
    const float* w1    = (const float*)d_in[4];
    const float* b1    = (const float*)d_in[5];
    const float* w2    = (const float*)d_in[6];
    const float* b2    = (const float*)d_in[7];
    const float* gamma = (const float*)d_in[8];
    const float* beta  = (const float*)d_in[9];
    const float* wout  = (const float*)d_in[10];
    const float* bout  = (const float*)d_in[11];
    float* out = (float*)d_out;

    k_init<<<(N_NODES + 255) / 256, 256>>>();
    k_detect<<<1, 32>>>(ei);
    k_prep<<<(9 * 4096 + 255) / 256, 256>>>(w1, w2);
    k_hist<<<(N_EDGES + 255) / 256, 256>>>(ei);
    k_scan<<<1, 1024>>>();
    k_fill<<<(N_EDGES + 255) / 256, 256>>>(ei);

    k_layer0<<<N_NODES / 8, 128>>>(x, w10, b1, b2);
    k_finalize<<<1, 64>>>(0, gamma, beta);
    for (int i = 1; i <= 4; i++) {
        k_gather<<<N_NODES / 4, 256>>>(i);
        k_mlp<<<N_NODES / 8, 256>>>(i, b1 + i * 64, b2 + i * 64);
        k_finalize<<<1, 64>>>(i, gamma + i * 64, beta + i * 64);
    }
    k_pool<<<256, 256>>>();
    k_final<<<1, 32>>>(wout, bout, out);
}